// round 2
// baseline (speedup 1.0000x reference)
#include <cuda_runtime.h>
#include <cuda_bf16.h>
#include <cstdint>

#define NN 50000
#define EE 800000
#define KF 256
#define HH 8

// Scratch (static device globals; no allocation in kernel_launch)
__device__ __align__(16) __nv_bfloat16 g_q[(size_t)NN * 256];
__device__ __align__(16) __nv_bfloat16 g_k[(size_t)NN * 256];
__device__ __align__(16) float g_sum[NN * HH];

// ---------------------------------------------------------------------------
// Fused QKV GEMM:  C[N,768] = x[N,256] @ [Wq;Wk;Wv]^T + [bq;bk;bv]
//   cols   0-255 -> g_q (bf16)
//   cols 256-511 -> g_k (bf16)
//   cols 512-767 -> out_v (f32), written TRANSPOSED per node: pos = d*8 + h
// Tiling: BM=64, BN=64, BK=16, 256 threads, 4x4 microtile per thread.
// ---------------------------------------------------------------------------
__global__ void __launch_bounds__(256) gemm_qkv(
    const float* __restrict__ x,
    const float* __restrict__ Wq, const float* __restrict__ bq,
    const float* __restrict__ Wk, const float* __restrict__ bk,
    const float* __restrict__ Wv, const float* __restrict__ bv,
    float* __restrict__ out_v)
{
    __shared__ float As[16][64];
    __shared__ float Bs[16][64];

    const int t  = threadIdx.x;
    const int tx = t & 15;        // 0..15 -> col quad
    const int ty = t >> 4;        // 0..15 -> row quad
    const int rowBase = blockIdx.y * 64;
    const int colBase = blockIdx.x * 64;

    // loader indices
    const int lr = t >> 2;          // 0..63
    const int lk = (t & 3) * 4;     // 0,4,8,12

    // B source: which weight matrix does this loader column belong to?
    const int gcL = colBase + lr;   // global output column for B loads (0..767)
    const float* Wm = (gcL < 256) ? Wq : (gcL < 512) ? Wk : Wv;
    const int wcL = gcL & 255;

    const int grL = rowBase + lr;   // global row for A loads
    const bool rowOK = (grL < NN);

    float acc[4][4];
#pragma unroll
    for (int i = 0; i < 4; i++)
#pragma unroll
        for (int j = 0; j < 4; j++) acc[i][j] = 0.f;

    for (int k0 = 0; k0 < KF; k0 += 16) {
        float4 a4 = rowOK ? *(const float4*)(x + (size_t)grL * KF + k0 + lk)
                          : make_float4(0.f, 0.f, 0.f, 0.f);
        float4 b4 = *(const float4*)(Wm + (size_t)wcL * KF + k0 + lk);
        As[lk + 0][lr] = a4.x; As[lk + 1][lr] = a4.y;
        As[lk + 2][lr] = a4.z; As[lk + 3][lr] = a4.w;
        Bs[lk + 0][lr] = b4.x; Bs[lk + 1][lr] = b4.y;
        Bs[lk + 2][lr] = b4.z; Bs[lk + 3][lr] = b4.w;
        __syncthreads();

#pragma unroll
        for (int kk = 0; kk < 16; kk++) {
            float4 av  = *(const float4*)&As[kk][ty << 2];
            float4 bv4 = *(const float4*)&Bs[kk][tx << 2];
            float a[4] = {av.x, av.y, av.z, av.w};
            float b[4] = {bv4.x, bv4.y, bv4.z, bv4.w};
#pragma unroll
            for (int i = 0; i < 4; i++)
#pragma unroll
                for (int j = 0; j < 4; j++) acc[i][j] += a[i] * b[j];
        }
        __syncthreads();
    }

    // Epilogue: bias + routing
    const int gcBase = colBase + (tx << 2);           // all 4 cols in same region
    const float* bptr = (gcBase < 256) ? bq : (gcBase < 512) ? bk : bv;
    const float4 bias4 = *(const float4*)(bptr + (gcBase & 255));
    const float bias[4] = {bias4.x, bias4.y, bias4.z, bias4.w};
    const int region = (gcBase < 256) ? 0 : (gcBase < 512) ? 1 : 2;

#pragma unroll
    for (int i = 0; i < 4; i++) {
        int gr = rowBase + (ty << 2) + i;
        if (gr >= NN) continue;
#pragma unroll
        for (int j = 0; j < 4; j++) {
            float val = acc[i][j] + bias[j];
            int wc = (gcBase & 255) + j;
            if (region == 0) {
                g_q[(size_t)gr * 256 + wc] = __float2bfloat16(val);
            } else if (region == 1) {
                g_k[(size_t)gr * 256 + wc] = __float2bfloat16(val);
            } else {
                // transpose: wc = h*32 + d  -> out pos = d*8 + h
                int h = wc >> 5, d = wc & 31;
                out_v[(size_t)gr * 256 + (d << 3) + h] = val;
            }
        }
    }
}

// ---------------------------------------------------------------------------
__global__ void zero_sum_kernel()
{
    int i = blockIdx.x * 256 + threadIdx.x;
    if (i < NN * HH) g_sum[i] = 0.f;
}

// ---------------------------------------------------------------------------
// Pass 1: per-edge logits -> exp -> out_att; atomicAdd into per-(src,head) sum.
// One warp per edge. lane = h*4 + sub ; each lane: 8 contiguous bf16 of q and k.
// ---------------------------------------------------------------------------
__global__ void __launch_bounds__(256) edge_pass1(
    const int* __restrict__ edge,
    const float* __restrict__ ew,
    float* __restrict__ out_att)
{
    const int e = blockIdx.x * 8 + (threadIdx.x >> 5);
    if (e >= EE) return;
    const int lane = threadIdx.x & 31;

    const int src = edge[e];
    const int dst = edge[EE + e];

    const uint4 qa = *(const uint4*)(g_q + (size_t)src * 256 + (lane << 3));
    const uint4 ka = *(const uint4*)(g_k + (size_t)dst * 256 + (lane << 3));

    float p = 0.f;
    {
        const unsigned qw[4] = {qa.x, qa.y, qa.z, qa.w};
        const unsigned kw[4] = {ka.x, ka.y, ka.z, ka.w};
#pragma unroll
        for (int c = 0; c < 4; c++) {
            __nv_bfloat162 q2 = *reinterpret_cast<const __nv_bfloat162*>(&qw[c]);
            __nv_bfloat162 k2 = *reinterpret_cast<const __nv_bfloat162*>(&kw[c]);
            float2 qf = __bfloat1622float2(q2);
            float2 kf = __bfloat1622float2(k2);
            p += qf.x * kf.x + qf.y * kf.y;
        }
    }
    // reduce across the 4 lanes of this head (sub = lane & 3)
    p += __shfl_xor_sync(0xffffffffu, p, 1);
    p += __shfl_xor_sync(0xffffffffu, p, 2);

    if ((lane & 3) == 0) {
        const int h = lane >> 2;
        const float w = ew[e];
        // 1/sqrt(32)
        const float ex = __expf(p * 0.17677669529663687f * w);
        out_att[(size_t)e * HH + h] = ex;
        atomicAdd(&g_sum[src * HH + h], ex);
    }
}

// ---------------------------------------------------------------------------
// Pass 2: normalize.  att[e,h] = ex[e,h] / (sum[src,h] + 1e-16)
// One thread per edge (8 heads via two float4s).
// ---------------------------------------------------------------------------
__global__ void __launch_bounds__(256) edge_pass2(
    const int* __restrict__ edge,
    float* __restrict__ out_att)
{
    const int e = blockIdx.x * 256 + threadIdx.x;
    if (e >= EE) return;
    const int src = edge[e];

    const float4* sp = (const float4*)(g_sum + src * HH);
    float4 s0 = sp[0], s1 = sp[1];

    float4* ap = (float4*)(out_att + (size_t)e * HH);
    float4 a0 = ap[0], a1 = ap[1];

    a0.x = __fdividef(a0.x, s0.x + 1e-16f);
    a0.y = __fdividef(a0.y, s0.y + 1e-16f);
    a0.z = __fdividef(a0.z, s0.z + 1e-16f);
    a0.w = __fdividef(a0.w, s0.w + 1e-16f);
    a1.x = __fdividef(a1.x, s1.x + 1e-16f);
    a1.y = __fdividef(a1.y, s1.y + 1e-16f);
    a1.z = __fdividef(a1.z, s1.z + 1e-16f);
    a1.w = __fdividef(a1.w, s1.w + 1e-16f);

    ap[0] = a0; ap[1] = a1;
}

// ---------------------------------------------------------------------------
extern "C" void kernel_launch(void* const* d_in, const int* in_sizes, int n_in,
                              void* d_out, int out_size)
{
    const float* x    = (const float*)d_in[0];
    const int*   edge = (const int*)d_in[1];
    const float* ew   = (const float*)d_in[2];
    const float* Wq   = (const float*)d_in[3];
    const float* bq   = (const float*)d_in[4];
    const float* Wk   = (const float*)d_in[5];
    const float* bk   = (const float*)d_in[6];
    const float* Wv   = (const float*)d_in[7];
    const float* bv   = (const float*)d_in[8];

    float* out_att = (float*)d_out;
    float* out_v   = out_att + (size_t)EE * HH;

    dim3 gemmGrid(768 / 64, (NN + 63) / 64);   // 12 x 782
    gemm_qkv<<<gemmGrid, 256>>>(x, Wq, bq, Wk, bk, Wv, bv, out_v);

    zero_sum_kernel<<<(NN * HH + 255) / 256, 256>>>();

    edge_pass1<<<EE / 8, 256>>>(edge, ew, out_att);

    edge_pass2<<<(EE + 255) / 256, 256>>>(edge, out_att);
}

// round 4
// speedup vs baseline: 1.9491x; 1.9491x over previous
#include <cuda_runtime.h>
#include <cuda_bf16.h>
#include <cstdint>

#define NN 50000
#define EE 800000
#define KF 256
#define HH 8
#define WROWS 768   // [Wq;Wk;Wv]

// ---------------------------------------------------------------------------
// Scratch (static device globals; no allocation anywhere)
// ---------------------------------------------------------------------------
__device__ __align__(16) __nv_bfloat16 g_q[(size_t)NN * 256];
__device__ __align__(16) __nv_bfloat16 g_k[(size_t)NN * 256];
__device__ __align__(16) float g_sum[NN * HH];
__device__ __align__(16) __nv_bfloat16 g_xhi[(size_t)NN * KF];
__device__ __align__(16) __nv_bfloat16 g_xlo[(size_t)NN * KF];
__device__ __align__(16) __nv_bfloat16 g_whi[(size_t)WROWS * KF];
__device__ __align__(16) __nv_bfloat16 g_wlo[(size_t)WROWS * KF];

// ---------------------------------------------------------------------------
__device__ __forceinline__ uint32_t smem_u32(const void* p) {
    uint32_t a;
    asm("{ .reg .u64 t; cvta.to.shared.u64 t, %1; cvt.u32.u64 %0, t; }" : "=r"(a) : "l"(p));
    return a;
}
__device__ __forceinline__ void ldsm_x4(uint32_t* r, uint32_t addr) {
    asm volatile("ldmatrix.sync.aligned.m8n8.x4.shared.b16 {%0,%1,%2,%3}, [%4];"
                 : "=r"(r[0]), "=r"(r[1]), "=r"(r[2]), "=r"(r[3]) : "r"(addr));
}
__device__ __forceinline__ void mma_bf16(float* c, const uint32_t* a, uint32_t b0, uint32_t b1) {
    asm volatile(
        "mma.sync.aligned.m16n8k16.row.col.f32.bf16.bf16.f32 "
        "{%0,%1,%2,%3}, {%4,%5,%6,%7}, {%8,%9}, {%0,%1,%2,%3};"
        : "+f"(c[0]), "+f"(c[1]), "+f"(c[2]), "+f"(c[3])
        : "r"(a[0]), "r"(a[1]), "r"(a[2]), "r"(a[3]), "r"(b0), "r"(b1));
}

// ---------------------------------------------------------------------------
// Convert pre-pass: x -> (g_xhi, g_xlo);  W concat -> (g_whi, g_wlo)
// ---------------------------------------------------------------------------
#define XGROUPS (NN * KF / 4)          // 3,200,000
#define WGROUPS (WROWS * KF / 4)       // 49,152
__global__ void __launch_bounds__(256) convert_split(
    const float* __restrict__ x,
    const float* __restrict__ Wq, const float* __restrict__ Wk, const float* __restrict__ Wv)
{
    int idx = blockIdx.x * 256 + threadIdx.x;
    if (idx >= XGROUPS + WGROUPS) return;

    const float* src;
    __nv_bfloat16 *dhi, *dlo;
    size_t off;
    if (idx < XGROUPS) {
        src = x; off = (size_t)idx * 4;
        dhi = g_xhi; dlo = g_xlo;
    } else {
        int widx = idx - XGROUPS;
        off = (size_t)widx * 4;
        size_t row = off / KF;
        const float* Wm = (row < 256) ? Wq : (row < 512) ? Wk : Wv;
        src = Wm - ((row < 256) ? 0 : (row < 512) ? 256 * KF : 512 * KF);
        dhi = g_whi; dlo = g_wlo;
    }
    float4 v = *(const float4*)(src + off);
    __nv_bfloat16 h0 = __float2bfloat16_rn(v.x);
    __nv_bfloat16 h1 = __float2bfloat16_rn(v.y);
    __nv_bfloat16 h2 = __float2bfloat16_rn(v.z);
    __nv_bfloat16 h3 = __float2bfloat16_rn(v.w);
    __nv_bfloat16 l0 = __float2bfloat16_rn(v.x - __bfloat162float(h0));
    __nv_bfloat16 l1 = __float2bfloat16_rn(v.y - __bfloat162float(h1));
    __nv_bfloat16 l2 = __float2bfloat16_rn(v.z - __bfloat162float(h2));
    __nv_bfloat16 l3 = __float2bfloat16_rn(v.w - __bfloat162float(h3));
    __nv_bfloat162 hp0(h0, h1), hp1(h2, h3), lp0(l0, l1), lp1(l2, l3);
    uint2 hu, lu;
    hu.x = *(uint32_t*)&hp0; hu.y = *(uint32_t*)&hp1;
    lu.x = *(uint32_t*)&lp0; lu.y = *(uint32_t*)&lp1;
    *(uint2*)(dhi + off) = hu;
    *(uint2*)(dlo + off) = lu;
}

// ---------------------------------------------------------------------------
// mma.sync QKV GEMM: C[N,768] = x @ W^T + b
//   blockIdx.x 0-3 (q,k cols): single-term bf16
//   blockIdx.x 4-5 (v cols):   3-term split-bf16 (fp32-grade)
// Tile BM=128, BN=128, K-slice 32; 8 warps, warp tile 32x64.
// ---------------------------------------------------------------------------
__global__ void __launch_bounds__(256) gemm_mma(
    const float* __restrict__ bq, const float* __restrict__ bk, const float* __restrict__ bv,
    float* __restrict__ out_v)
{
    __shared__ __align__(16) __nv_bfloat16 sA[128][40];
    __shared__ __align__(16) __nv_bfloat16 sB[128][40];

    const int t = threadIdx.x;
    const int wid = t >> 5;
    const int lane = t & 31;
    const int nt = blockIdx.x;      // 0..5
    const int mT = blockIdx.y;      // 0..390
    const bool isV = (nt >= 4);
    const int nterms = isV ? 3 : 1;

    const int wm = (wid >> 1) * 32;     // warp m offset in tile
    const int wn = (wid & 1) * 64;      // warp n offset in tile

    const uint32_t sAb = smem_u32(&sA[0][0]);
    const uint32_t sBb = smem_u32(&sB[0][0]);

    // ldmatrix per-lane base addresses
    const int rA = (lane & 15);
    const int cA = (lane >> 4) << 3;                  // 0 or 8
    const int rB = (lane & 7) + ((lane >> 4) << 3);   // 0..15
    const int cB = ((lane >> 3) & 1) << 3;            // 0 or 8

    uint32_t addrA[2], addrB[4];
#pragma unroll
    for (int mi = 0; mi < 2; mi++)
        addrA[mi] = sAb + (uint32_t)(wm + mi * 16 + rA) * 80u + (uint32_t)cA * 2u;
#pragma unroll
    for (int nf4 = 0; nf4 < 4; nf4++)
        addrB[nf4] = sBb + (uint32_t)(wn + nf4 * 16 + rB) * 80u + (uint32_t)cB * 2u;

    float acc[2][8][4];
#pragma unroll
    for (int mi = 0; mi < 2; mi++)
#pragma unroll
        for (int nf = 0; nf < 8; nf++)
#pragma unroll
            for (int i = 0; i < 4; i++) acc[mi][nf][i] = 0.f;

    // loader indices
    const int lrow = t >> 1;            // 0..127
    const int lcg = (t & 1) * 16;       // 0 or 16
    const int growL = mT * 128 + lrow;
    const bool rowOK = (growL < NN);
    const int brow = nt * 128 + lrow;   // < 768 always

    for (int term = 0; term < nterms; term++) {
        const __nv_bfloat16* Asrc = (term == 2) ? g_xlo : g_xhi;
        const __nv_bfloat16* Bsrc = (term == 1) ? g_wlo : g_whi;

        for (int s = 0; s < 8; s++) {
            __syncthreads();   // protect SMEM from previous iteration's readers
            // ---- load A[128x32], B[128x32] slice ----
            uint4 a0 = make_uint4(0, 0, 0, 0), a1 = make_uint4(0, 0, 0, 0);
            if (rowOK) {
                const __nv_bfloat16* ap = Asrc + (size_t)growL * KF + s * 32 + lcg;
                a0 = *(const uint4*)ap;
                a1 = *(const uint4*)(ap + 8);
            }
            *(uint4*)&sA[lrow][lcg] = a0;
            *(uint4*)&sA[lrow][lcg + 8] = a1;
            const __nv_bfloat16* bp = Bsrc + (size_t)brow * KF + s * 32 + lcg;
            *(uint4*)&sB[lrow][lcg] = *(const uint4*)bp;
            *(uint4*)&sB[lrow][lcg + 8] = *(const uint4*)(bp + 8);
            __syncthreads();

            // ---- compute: 2 x k16 ----
#pragma unroll
            for (int kk = 0; kk < 2; kk++) {
                uint32_t afrag[2][4];
                ldsm_x4(afrag[0], addrA[0] + kk * 32);
                ldsm_x4(afrag[1], addrA[1] + kk * 32);
                uint32_t bfrag[4][4];
#pragma unroll
                for (int nf4 = 0; nf4 < 4; nf4++)
                    ldsm_x4(bfrag[nf4], addrB[nf4] + kk * 32);
#pragma unroll
                for (int mi = 0; mi < 2; mi++)
#pragma unroll
                    for (int nf = 0; nf < 8; nf++)
                        mma_bf16(acc[mi][nf], afrag[mi],
                                 bfrag[nf >> 1][(nf & 1) * 2],
                                 bfrag[nf >> 1][(nf & 1) * 2 + 1]);
            }
        }
    }

    // ---- epilogue ----
    const int g = lane >> 2, tg = lane & 3;
#pragma unroll
    for (int mi = 0; mi < 2; mi++) {
        const int r0 = wm + mi * 16 + g;
#pragma unroll
        for (int half = 0; half < 2; half++) {     // d0,d1 vs d2,d3 (row, row+8)
            const int gr = mT * 128 + r0 + half * 8;
            if (gr >= NN) continue;
#pragma unroll
            for (int nf = 0; nf < 8; nf++) {
                const int c0 = wn + nf * 8 + tg * 2;   // block-local col, even
                float v0 = acc[mi][nf][half * 2];
                float v1 = acc[mi][nf][half * 2 + 1];
                if (!isV) {
                    const bool isQ = (nt < 2);
                    const int lc = (nt & 1) * 128 + c0;   // col within 256
                    const float* bptr = isQ ? bq : bk;
                    v0 += __ldg(bptr + lc);
                    v1 += __ldg(bptr + lc + 1);
                    __nv_bfloat16* dst = isQ ? g_q : g_k;
                    __nv_bfloat162 p2 = __floats2bfloat162_rn(v0, v1);
                    *(__nv_bfloat162*)(dst + (size_t)gr * 256 + lc) = p2;
                } else {
                    const int wc = (nt - 4) * 128 + c0;   // col within 256 (v)
                    v0 += __ldg(bv + wc);
                    v1 += __ldg(bv + wc + 1);
                    const int h = wc >> 5, d = wc & 31;
                    float* vp = out_v + (size_t)gr * 256 + d * 8 + h;
                    vp[0] = v0;
                    vp[8] = v1;   // (d+1)*8 + h
                }
            }
        }
    }
}

// ---------------------------------------------------------------------------
__global__ void zero_sum_kernel()
{
    int i = blockIdx.x * 256 + threadIdx.x;
    if (i < NN * HH) g_sum[i] = 0.f;
}

// ---------------------------------------------------------------------------
// Pass 1: per-edge logits -> exp -> out_att; atomicAdd per-(src,head) sum.
// ---------------------------------------------------------------------------
__global__ void __launch_bounds__(256) edge_pass1(
    const int* __restrict__ edge,
    const float* __restrict__ ew,
    float* __restrict__ out_att)
{
    const int e = blockIdx.x * 8 + (threadIdx.x >> 5);
    if (e >= EE) return;
    const int lane = threadIdx.x & 31;

    const int src = edge[e];
    const int dst = edge[EE + e];

    const uint4 qa = *(const uint4*)(g_q + (size_t)src * 256 + (lane << 3));
    const uint4 ka = *(const uint4*)(g_k + (size_t)dst * 256 + (lane << 3));

    float p = 0.f;
    {
        const unsigned qw[4] = {qa.x, qa.y, qa.z, qa.w};
        const unsigned kw[4] = {ka.x, ka.y, ka.z, ka.w};
#pragma unroll
        for (int c = 0; c < 4; c++) {
            __nv_bfloat162 q2 = *reinterpret_cast<const __nv_bfloat162*>(&qw[c]);
            __nv_bfloat162 k2 = *reinterpret_cast<const __nv_bfloat162*>(&kw[c]);
            float2 qf = __bfloat1622float2(q2);
            float2 kf = __bfloat1622float2(k2);
            p += qf.x * kf.x + qf.y * kf.y;
        }
    }
    p += __shfl_xor_sync(0xffffffffu, p, 1);
    p += __shfl_xor_sync(0xffffffffu, p, 2);

    if ((lane & 3) == 0) {
        const int h = lane >> 2;
        const float w = ew[e];
        const float ex = __expf(p * 0.17677669529663687f * w);   // 1/sqrt(32)
        out_att[(size_t)e * HH + h] = ex;
        atomicAdd(&g_sum[src * HH + h], ex);
    }
}

// ---------------------------------------------------------------------------
// Pass 2: normalize.
// ---------------------------------------------------------------------------
__global__ void __launch_bounds__(256) edge_pass2(
    const int* __restrict__ edge,
    float* __restrict__ out_att)
{
    const int e = blockIdx.x * 256 + threadIdx.x;
    if (e >= EE) return;
    const int src = edge[e];

    const float4* sp = (const float4*)(g_sum + src * HH);
    float4 s0 = sp[0], s1 = sp[1];

    float4* ap = (float4*)(out_att + (size_t)e * HH);
    float4 a0 = ap[0], a1 = ap[1];

    a0.x = __fdividef(a0.x, s0.x + 1e-16f);
    a0.y = __fdividef(a0.y, s0.y + 1e-16f);
    a0.z = __fdividef(a0.z, s0.z + 1e-16f);
    a0.w = __fdividef(a0.w, s0.w + 1e-16f);
    a1.x = __fdividef(a1.x, s1.x + 1e-16f);
    a1.y = __fdividef(a1.y, s1.y + 1e-16f);
    a1.z = __fdividef(a1.z, s1.z + 1e-16f);
    a1.w = __fdividef(a1.w, s1.w + 1e-16f);

    ap[0] = a0; ap[1] = a1;
}

// ---------------------------------------------------------------------------
extern "C" void kernel_launch(void* const* d_in, const int* in_sizes, int n_in,
                              void* d_out, int out_size)
{
    const float* x    = (const float*)d_in[0];
    const int*   edge = (const int*)d_in[1];
    const float* ew   = (const float*)d_in[2];
    const float* Wq   = (const float*)d_in[3];
    const float* bq   = (const float*)d_in[4];
    const float* Wk   = (const float*)d_in[5];
    const float* bk   = (const float*)d_in[6];
    const float* Wv   = (const float*)d_in[7];
    const float* bv   = (const float*)d_in[8];

    float* out_att = (float*)d_out;
    float* out_v   = out_att + (size_t)EE * HH;

    convert_split<<<(XGROUPS + WGROUPS + 255) / 256, 256>>>(x, Wq, Wk, Wv);

    zero_sum_kernel<<<(NN * HH + 255) / 256, 256>>>();

    dim3 gGrid(6, (NN + 127) / 128);   // 6 x 391
    gemm_mma<<<gGrid, 256>>>(bq, bk, bv, out_v);

    edge_pass1<<<EE / 8, 256>>>(edge, ew, out_att);

    edge_pass2<<<(EE + 255) / 256, 256>>>(edge, out_att);
}

// round 5
// speedup vs baseline: 2.2405x; 1.1495x over previous
#include <cuda_runtime.h>
#include <cuda_bf16.h>
#include <cstdint>

#define NN 50000
#define EE 800000
#define KF 256
#define HH 8
#define WROWS 768   // [Wq;Wk;Wv]

// ---------------------------------------------------------------------------
// Scratch (static device globals; no allocation anywhere)
// ---------------------------------------------------------------------------
__device__ __align__(16) __nv_bfloat16 g_q[(size_t)NN * 256];
__device__ __align__(16) __nv_bfloat16 g_k[(size_t)NN * 256];
__device__ __align__(16) float g_sum[NN * HH];
__device__ __align__(16) __nv_bfloat16 g_xhi[(size_t)NN * KF];
__device__ __align__(16) __nv_bfloat16 g_xlo[(size_t)NN * KF];
__device__ __align__(16) __nv_bfloat16 g_whi[(size_t)WROWS * KF];
__device__ __align__(16) __nv_bfloat16 g_wlo[(size_t)WROWS * KF];

// ---------------------------------------------------------------------------
__device__ __forceinline__ uint32_t smem_u32(const void* p) {
    uint32_t a;
    asm("{ .reg .u64 t; cvta.to.shared.u64 t, %1; cvt.u32.u64 %0, t; }" : "=r"(a) : "l"(p));
    return a;
}
__device__ __forceinline__ void ldsm_x4(uint32_t* r, uint32_t addr) {
    asm volatile("ldmatrix.sync.aligned.m8n8.x4.shared.b16 {%0,%1,%2,%3}, [%4];"
                 : "=r"(r[0]), "=r"(r[1]), "=r"(r[2]), "=r"(r[3]) : "r"(addr));
}
__device__ __forceinline__ void mma_bf16(float* c, const uint32_t* a, uint32_t b0, uint32_t b1) {
    asm volatile(
        "mma.sync.aligned.m16n8k16.row.col.f32.bf16.bf16.f32 "
        "{%0,%1,%2,%3}, {%4,%5,%6,%7}, {%8,%9}, {%0,%1,%2,%3};"
        : "+f"(c[0]), "+f"(c[1]), "+f"(c[2]), "+f"(c[3])
        : "r"(a[0]), "r"(a[1]), "r"(a[2]), "r"(a[3]), "r"(b0), "r"(b1));
}
__device__ __forceinline__ void cp_async16(uint32_t smem_addr, const void* gptr, uint32_t src_bytes) {
    asm volatile("cp.async.cg.shared.global [%0], [%1], 16, %2;"
                 :: "r"(smem_addr), "l"(gptr), "r"(src_bytes) : "memory");
}
#define CP_COMMIT() asm volatile("cp.async.commit_group;" ::: "memory")
#define CP_WAIT(n)  asm volatile("cp.async.wait_group %0;" :: "n"(n) : "memory")

// ---------------------------------------------------------------------------
// Convert pre-pass: x -> (g_xhi, g_xlo);  W concat -> (g_whi, g_wlo);
// also zeroes g_sum (tail index range).
// ---------------------------------------------------------------------------
#define XGROUPS (NN * KF / 4)          // 3,200,000
#define WGROUPS (WROWS * KF / 4)       // 49,152
#define ZGROUPS (NN * HH / 4)          // 100,000
__global__ void __launch_bounds__(256) convert_split(
    const float* __restrict__ x,
    const float* __restrict__ Wq, const float* __restrict__ Wk, const float* __restrict__ Wv)
{
    int idx = blockIdx.x * 256 + threadIdx.x;
    if (idx >= XGROUPS + WGROUPS) {
        int z = idx - (XGROUPS + WGROUPS);
        if (z < ZGROUPS)
            *(float4*)(g_sum + (size_t)z * 4) = make_float4(0.f, 0.f, 0.f, 0.f);
        return;
    }

    const float* src;
    __nv_bfloat16 *dhi, *dlo;
    size_t off;
    if (idx < XGROUPS) {
        src = x; off = (size_t)idx * 4;
        dhi = g_xhi; dlo = g_xlo;
    } else {
        int widx = idx - XGROUPS;
        off = (size_t)widx * 4;
        size_t row = off / KF;
        const float* Wm = (row < 256) ? Wq : (row < 512) ? Wk : Wv;
        src = Wm - ((row < 256) ? 0 : (row < 512) ? 256 * KF : 512 * KF);
        dhi = g_whi; dlo = g_wlo;
    }
    float4 v = *(const float4*)(src + off);
    __nv_bfloat16 h0 = __float2bfloat16_rn(v.x);
    __nv_bfloat16 h1 = __float2bfloat16_rn(v.y);
    __nv_bfloat16 h2 = __float2bfloat16_rn(v.z);
    __nv_bfloat16 h3 = __float2bfloat16_rn(v.w);
    __nv_bfloat16 l0 = __float2bfloat16_rn(v.x - __bfloat162float(h0));
    __nv_bfloat16 l1 = __float2bfloat16_rn(v.y - __bfloat162float(h1));
    __nv_bfloat16 l2 = __float2bfloat16_rn(v.z - __bfloat162float(h2));
    __nv_bfloat16 l3 = __float2bfloat16_rn(v.w - __bfloat162float(h3));
    __nv_bfloat162 hp0(h0, h1), hp1(h2, h3), lp0(l0, l1), lp1(l2, l3);
    uint2 hu, lu;
    hu.x = *(uint32_t*)&hp0; hu.y = *(uint32_t*)&hp1;
    lu.x = *(uint32_t*)&lp0; lu.y = *(uint32_t*)&lp1;
    *(uint2*)(dhi + off) = hu;
    *(uint2*)(dlo + off) = lu;
}

// ---------------------------------------------------------------------------
// Pipelined mma.sync QKV GEMM: C[N,768] = x @ W^T + b
//   blockIdx.x 0-3 (q,k cols): single-term bf16
//   blockIdx.x 4-5 (v cols):   3-term split-bf16 (fp32-grade)
// BM=128, BN=128, BK=32; 8 warps (32x64 warp tile); 2-stage cp.async pipeline.
// ---------------------------------------------------------------------------
#define SSTRIDE 10240u   // bytes per stage per tensor: 128*40*2

__global__ void __launch_bounds__(256) gemm_mma(
    const float* __restrict__ bq, const float* __restrict__ bk, const float* __restrict__ bv,
    float* __restrict__ out_v)
{
    __shared__ __align__(16) __nv_bfloat16 sA[2][128][40];
    __shared__ __align__(16) __nv_bfloat16 sB[2][128][40];

    const int t = threadIdx.x;
    const int wid = t >> 5;
    const int lane = t & 31;
    const int nt = blockIdx.x;      // 0..5
    const int mT = blockIdx.y;      // 0..390
    const bool isV = (nt >= 4);
    const int S = isV ? 24 : 8;     // flat slices: term = s>>3, ks = s&7

    const int wm = (wid >> 1) * 32;
    const int wn = (wid & 1) * 64;

    const uint32_t sAb = smem_u32(&sA[0][0][0]);
    const uint32_t sBb = smem_u32(&sB[0][0][0]);

    // ldmatrix per-lane base addresses (stage 0)
    const int rA = (lane & 15);
    const int cA = (lane >> 4) << 3;
    const int rB = (lane & 7) + ((lane >> 4) << 3);
    const int cB = ((lane >> 3) & 1) << 3;

    uint32_t addrA[2], addrB[4];
#pragma unroll
    for (int mi = 0; mi < 2; mi++)
        addrA[mi] = sAb + (uint32_t)(wm + mi * 16 + rA) * 80u + (uint32_t)cA * 2u;
#pragma unroll
    for (int nf4 = 0; nf4 < 4; nf4++)
        addrB[nf4] = sBb + (uint32_t)(wn + nf4 * 16 + rB) * 80u + (uint32_t)cB * 2u;

    float acc[2][8][4];
#pragma unroll
    for (int mi = 0; mi < 2; mi++)
#pragma unroll
        for (int nf = 0; nf < 8; nf++)
#pragma unroll
            for (int i = 0; i < 4; i++) acc[mi][nf][i] = 0.f;

    // loader mapping: row = t>>1, col group = (t&1)*16 (two 16B chunks)
    const int lrow = t >> 1;
    const int lcg = (t & 1) * 16;
    const int growL = mT * 128 + lrow;
    const uint32_t aBytes = (growL < NN) ? 16u : 0u;
    const int brow = nt * 128 + lrow;

    const uint32_t dstA0 = sAb + (uint32_t)lrow * 80u + (uint32_t)lcg * 2u;
    const uint32_t dstB0 = sBb + (uint32_t)lrow * 80u + (uint32_t)lcg * 2u;

    // issue stage for slice s into buffer (s&1)
    auto issue = [&](int s) {
        const int term = s >> 3, ks = s & 7;
        const __nv_bfloat16* Asrc = (term == 2) ? g_xlo : g_xhi;
        const __nv_bfloat16* Bsrc = (term == 1) ? g_wlo : g_whi;
        const uint32_t st = (uint32_t)(s & 1) * SSTRIDE;
        const __nv_bfloat16* ap = Asrc + (size_t)growL * KF + ks * 32 + lcg;
        const __nv_bfloat16* bp = Bsrc + (size_t)brow * KF + ks * 32 + lcg;
        cp_async16(dstA0 + st, ap, aBytes);
        cp_async16(dstA0 + st + 16, ap + 8, aBytes);
        cp_async16(dstB0 + st, bp, 16u);
        cp_async16(dstB0 + st + 16, bp + 8, 16u);
        CP_COMMIT();
    };

    issue(0);
    for (int s = 0; s < S; s++) {
        if (s + 1 < S) { issue(s + 1); CP_WAIT(1); }
        else           { CP_WAIT(0); }
        __syncthreads();

        const uint32_t st = (uint32_t)(s & 1) * SSTRIDE;
#pragma unroll
        for (int kk = 0; kk < 2; kk++) {
            uint32_t afrag[2][4];
            ldsm_x4(afrag[0], addrA[0] + st + kk * 32);
            ldsm_x4(afrag[1], addrA[1] + st + kk * 32);
            uint32_t bfrag[4][4];
#pragma unroll
            for (int nf4 = 0; nf4 < 4; nf4++)
                ldsm_x4(bfrag[nf4], addrB[nf4] + st + kk * 32);
#pragma unroll
            for (int mi = 0; mi < 2; mi++)
#pragma unroll
                for (int nf = 0; nf < 8; nf++)
                    mma_bf16(acc[mi][nf], afrag[mi],
                             bfrag[nf >> 1][(nf & 1) * 2],
                             bfrag[nf >> 1][(nf & 1) * 2 + 1]);
        }
        __syncthreads();
    }

    // ---- epilogue ----
    const int g = lane >> 2, tg = lane & 3;
#pragma unroll
    for (int mi = 0; mi < 2; mi++) {
        const int r0 = wm + mi * 16 + g;
#pragma unroll
        for (int half = 0; half < 2; half++) {
            const int gr = mT * 128 + r0 + half * 8;
            if (gr >= NN) continue;
#pragma unroll
            for (int nf = 0; nf < 8; nf++) {
                const int c0 = wn + nf * 8 + tg * 2;
                float v0 = acc[mi][nf][half * 2];
                float v1 = acc[mi][nf][half * 2 + 1];
                if (!isV) {
                    const bool isQ = (nt < 2);
                    const int lc = (nt & 1) * 128 + c0;
                    const float* bptr = isQ ? bq : bk;
                    v0 += __ldg(bptr + lc);
                    v1 += __ldg(bptr + lc + 1);
                    __nv_bfloat16* dst = isQ ? g_q : g_k;
                    __nv_bfloat162 p2 = __floats2bfloat162_rn(v0, v1);
                    *(__nv_bfloat162*)(dst + (size_t)gr * 256 + lc) = p2;
                } else {
                    const int wc = (nt - 4) * 128 + c0;
                    v0 += __ldg(bv + wc);
                    v1 += __ldg(bv + wc + 1);
                    const int h = wc >> 5, d = wc & 31;
                    float* vp = out_v + (size_t)gr * 256 + d * 8 + h;
                    vp[0] = v0;
                    vp[8] = v1;
                }
            }
        }
    }
}

// ---------------------------------------------------------------------------
// Pass 1: 8 lanes per edge (one lane per head), 4 edges per warp.
// Each lane: dot(q[src,h*32:+32], k[dst,h*32:+32]) -> exp -> store + atomic.
// ---------------------------------------------------------------------------
__global__ void __launch_bounds__(256) edge_pass1(
    const int* __restrict__ edge,
    const float* __restrict__ ew,
    float* __restrict__ out_att)
{
    const int lane = threadIdx.x & 31;
    const int wid = threadIdx.x >> 5;
    const int e = blockIdx.x * 32 + wid * 4 + (lane >> 3);
    if (e >= EE) return;
    const int h = lane & 7;

    const int src = __ldg(edge + e);
    const int dst = __ldg(edge + EE + e);
    const float w = __ldg(ew + e);

    const uint4* qp = (const uint4*)(g_q + (size_t)src * 256 + h * 32);
    const uint4* kp = (const uint4*)(g_k + (size_t)dst * 256 + h * 32);

    // front-batched loads (MLP=8)
    uint4 q0 = qp[0], q1 = qp[1], q2 = qp[2], q3 = qp[3];
    uint4 k0 = kp[0], k1 = kp[1], k2 = kp[2], k3 = kp[3];

    float p = 0.f;
    const uint32_t qw[16] = {q0.x, q0.y, q0.z, q0.w, q1.x, q1.y, q1.z, q1.w,
                             q2.x, q2.y, q2.z, q2.w, q3.x, q3.y, q3.z, q3.w};
    const uint32_t kw[16] = {k0.x, k0.y, k0.z, k0.w, k1.x, k1.y, k1.z, k1.w,
                             k2.x, k2.y, k2.z, k2.w, k3.x, k3.y, k3.z, k3.w};
#pragma unroll
    for (int c = 0; c < 16; c++) {
        float2 qf = __bfloat1622float2(*reinterpret_cast<const __nv_bfloat162*>(&qw[c]));
        float2 kf = __bfloat1622float2(*reinterpret_cast<const __nv_bfloat162*>(&kw[c]));
        p = fmaf(qf.x, kf.x, p);
        p = fmaf(qf.y, kf.y, p);
    }

    const float ex = __expf(p * 0.17677669529663687f * w);   // 1/sqrt(32)
    out_att[(size_t)e * HH + h] = ex;                         // warp-coalesced
    atomicAdd(&g_sum[src * HH + h], ex);
}

// ---------------------------------------------------------------------------
// Pass 2: normalize.
// ---------------------------------------------------------------------------
__global__ void __launch_bounds__(256) edge_pass2(
    const int* __restrict__ edge,
    float* __restrict__ out_att)
{
    const int e = blockIdx.x * 256 + threadIdx.x;
    if (e >= EE) return;
    const int src = edge[e];

    const float4* sp = (const float4*)(g_sum + src * HH);
    float4 s0 = sp[0], s1 = sp[1];

    float4* ap = (float4*)(out_att + (size_t)e * HH);
    float4 a0 = ap[0], a1 = ap[1];

    a0.x = __fdividef(a0.x, s0.x + 1e-16f);
    a0.y = __fdividef(a0.y, s0.y + 1e-16f);
    a0.z = __fdividef(a0.z, s0.z + 1e-16f);
    a0.w = __fdividef(a0.w, s0.w + 1e-16f);
    a1.x = __fdividef(a1.x, s1.x + 1e-16f);
    a1.y = __fdividef(a1.y, s1.y + 1e-16f);
    a1.z = __fdividef(a1.z, s1.z + 1e-16f);
    a1.w = __fdividef(a1.w, s1.w + 1e-16f);

    ap[0] = a0; ap[1] = a1;
}

// ---------------------------------------------------------------------------
extern "C" void kernel_launch(void* const* d_in, const int* in_sizes, int n_in,
                              void* d_out, int out_size)
{
    const float* x    = (const float*)d_in[0];
    const int*   edge = (const int*)d_in[1];
    const float* ew   = (const float*)d_in[2];
    const float* Wq   = (const float*)d_in[3];
    const float* bq   = (const float*)d_in[4];
    const float* Wk   = (const float*)d_in[5];
    const float* bk   = (const float*)d_in[6];
    const float* Wv   = (const float*)d_in[7];
    const float* bv   = (const float*)d_in[8];

    float* out_att = (float*)d_out;
    float* out_v   = out_att + (size_t)EE * HH;

    convert_split<<<(XGROUPS + WGROUPS + ZGROUPS + 255) / 256, 256>>>(x, Wq, Wk, Wv);

    dim3 gGrid(6, (NN + 127) / 128);   // 6 x 391
    gemm_mma<<<gGrid, 256>>>(bq, bk, bv, out_v);

    edge_pass1<<<EE / 32, 256>>>(edge, ew, out_att);

    edge_pass2<<<(EE + 255) / 256, 256>>>(edge, out_att);
}

// round 6
// speedup vs baseline: 2.7851x; 1.2431x over previous
#include <cuda_runtime.h>
#include <cuda_fp16.h>
#include <cstdint>

#define NN 50000
#define EE 800000
#define KF 256
#define HH 8
#define WROWS 768   // [Wq;Wk;Wv]

// ---------------------------------------------------------------------------
// Scratch (static device globals; no allocation anywhere)
// ---------------------------------------------------------------------------
__device__ __align__(16) __half g_q[(size_t)NN * 256];
__device__ __align__(16) __half g_k[(size_t)NN * 256];
__device__ __align__(16) float g_sum[NN * HH];
__device__ __align__(16) __half g_xh[(size_t)NN * KF];
__device__ __align__(16) __half g_wh[(size_t)WROWS * KF];

// ---------------------------------------------------------------------------
__device__ __forceinline__ uint32_t smem_u32(const void* p) {
    uint32_t a;
    asm("{ .reg .u64 t; cvta.to.shared.u64 t, %1; cvt.u32.u64 %0, t; }" : "=r"(a) : "l"(p));
    return a;
}
__device__ __forceinline__ void ldsm_x4(uint32_t* r, uint32_t addr) {
    asm volatile("ldmatrix.sync.aligned.m8n8.x4.shared.b16 {%0,%1,%2,%3}, [%4];"
                 : "=r"(r[0]), "=r"(r[1]), "=r"(r[2]), "=r"(r[3]) : "r"(addr));
}
__device__ __forceinline__ void mma_f16(float* c, const uint32_t* a, uint32_t b0, uint32_t b1) {
    asm volatile(
        "mma.sync.aligned.m16n8k16.row.col.f32.f16.f16.f32 "
        "{%0,%1,%2,%3}, {%4,%5,%6,%7}, {%8,%9}, {%0,%1,%2,%3};"
        : "+f"(c[0]), "+f"(c[1]), "+f"(c[2]), "+f"(c[3])
        : "r"(a[0]), "r"(a[1]), "r"(a[2]), "r"(a[3]), "r"(b0), "r"(b1));
}
__device__ __forceinline__ void cp_async16(uint32_t smem_addr, const void* gptr, uint32_t src_bytes) {
    asm volatile("cp.async.cg.shared.global [%0], [%1], 16, %2;"
                 :: "r"(smem_addr), "l"(gptr), "r"(src_bytes) : "memory");
}
#define CP_COMMIT() asm volatile("cp.async.commit_group;" ::: "memory")
#define CP_WAIT(n)  asm volatile("cp.async.wait_group %0;" :: "n"(n) : "memory")

// ---------------------------------------------------------------------------
// Convert pre-pass: x -> g_xh (fp16); W concat -> g_wh (fp16); zero g_sum.
// ---------------------------------------------------------------------------
#define XGROUPS (NN * KF / 4)          // 3,200,000
#define WGROUPS (WROWS * KF / 4)       // 49,152
#define ZGROUPS (NN * HH / 4)          // 100,000
__global__ void __launch_bounds__(256) convert_fp16(
    const float* __restrict__ x,
    const float* __restrict__ Wq, const float* __restrict__ Wk, const float* __restrict__ Wv)
{
    int idx = blockIdx.x * 256 + threadIdx.x;
    if (idx >= XGROUPS + WGROUPS) {
        int z = idx - (XGROUPS + WGROUPS);
        if (z < ZGROUPS)
            *(float4*)(g_sum + (size_t)z * 4) = make_float4(0.f, 0.f, 0.f, 0.f);
        return;
    }

    const float* src;
    __half* dst;
    size_t off;
    if (idx < XGROUPS) {
        src = x; off = (size_t)idx * 4;
        dst = g_xh;
    } else {
        int widx = idx - XGROUPS;
        off = (size_t)widx * 4;
        size_t row = off / KF;
        const float* Wm = (row < 256) ? Wq : (row < 512) ? Wk : Wv;
        src = Wm - ((row < 256) ? 0 : (row < 512) ? 256 * KF : 512 * KF);
        dst = g_wh;
    }
    float4 v = *(const float4*)(src + off);
    __half2 p0 = __floats2half2_rn(v.x, v.y);
    __half2 p1 = __floats2half2_rn(v.z, v.w);
    uint2 u;
    u.x = *(uint32_t*)&p0; u.y = *(uint32_t*)&p1;
    *(uint2*)(dst + off) = u;
}

// ---------------------------------------------------------------------------
// Pipelined mma.sync QKV GEMM (fp16, single-term): C[N,768] = x @ W^T + b
// BM=128, BN=128, BK=32; 8 warps (32x64 warp tile); 2-stage cp.async pipeline.
// Routing: nt 0-1 -> g_q | nt 2-3 -> g_k | nt 4-5 -> out_v (f32, transposed)
// ---------------------------------------------------------------------------
#define SSTRIDE 10240u   // bytes per stage per tensor: 128*40*2

__global__ void __launch_bounds__(256) gemm_mma(
    const float* __restrict__ bq, const float* __restrict__ bk, const float* __restrict__ bv,
    float* __restrict__ out_v)
{
    __shared__ __align__(16) __half sA[2][128][40];
    __shared__ __align__(16) __half sB[2][128][40];

    const int t = threadIdx.x;
    const int wid = t >> 5;
    const int lane = t & 31;
    const int nt = blockIdx.x;      // 0..5
    const int mT = blockIdx.y;      // 0..390
    const bool isV = (nt >= 4);

    const int wm = (wid >> 1) * 32;
    const int wn = (wid & 1) * 64;

    const uint32_t sAb = smem_u32(&sA[0][0][0]);
    const uint32_t sBb = smem_u32(&sB[0][0][0]);

    const int rA = (lane & 15);
    const int cA = (lane >> 4) << 3;
    const int rB = (lane & 7) + ((lane >> 4) << 3);
    const int cB = ((lane >> 3) & 1) << 3;

    uint32_t addrA[2], addrB[4];
#pragma unroll
    for (int mi = 0; mi < 2; mi++)
        addrA[mi] = sAb + (uint32_t)(wm + mi * 16 + rA) * 80u + (uint32_t)cA * 2u;
#pragma unroll
    for (int nf4 = 0; nf4 < 4; nf4++)
        addrB[nf4] = sBb + (uint32_t)(wn + nf4 * 16 + rB) * 80u + (uint32_t)cB * 2u;

    float acc[2][8][4];
#pragma unroll
    for (int mi = 0; mi < 2; mi++)
#pragma unroll
        for (int nf = 0; nf < 8; nf++)
#pragma unroll
            for (int i = 0; i < 4; i++) acc[mi][nf][i] = 0.f;

    const int lrow = t >> 1;
    const int lcg = (t & 1) * 16;
    const int growL = mT * 128 + lrow;
    const uint32_t aBytes = (growL < NN) ? 16u : 0u;
    const int brow = nt * 128 + lrow;

    const uint32_t dstA0 = sAb + (uint32_t)lrow * 80u + (uint32_t)lcg * 2u;
    const uint32_t dstB0 = sBb + (uint32_t)lrow * 80u + (uint32_t)lcg * 2u;

    auto issue = [&](int s) {
        const uint32_t st = (uint32_t)(s & 1) * SSTRIDE;
        const __half* ap = g_xh + (size_t)growL * KF + s * 32 + lcg;
        const __half* bp = g_wh + (size_t)brow * KF + s * 32 + lcg;
        cp_async16(dstA0 + st, ap, aBytes);
        cp_async16(dstA0 + st + 16, ap + 8, aBytes);
        cp_async16(dstB0 + st, bp, 16u);
        cp_async16(dstB0 + st + 16, bp + 8, 16u);
        CP_COMMIT();
    };

    issue(0);
#pragma unroll
    for (int s = 0; s < 8; s++) {
        if (s + 1 < 8) { issue(s + 1); CP_WAIT(1); }
        else           { CP_WAIT(0); }
        __syncthreads();

        const uint32_t st = (uint32_t)(s & 1) * SSTRIDE;
#pragma unroll
        for (int kk = 0; kk < 2; kk++) {
            uint32_t afrag[2][4];
            ldsm_x4(afrag[0], addrA[0] + st + kk * 32);
            ldsm_x4(afrag[1], addrA[1] + st + kk * 32);
            uint32_t bfrag[4][4];
#pragma unroll
            for (int nf4 = 0; nf4 < 4; nf4++)
                ldsm_x4(bfrag[nf4], addrB[nf4] + st + kk * 32);
#pragma unroll
            for (int mi = 0; mi < 2; mi++)
#pragma unroll
                for (int nf = 0; nf < 8; nf++)
                    mma_f16(acc[mi][nf], afrag[mi],
                            bfrag[nf >> 1][(nf & 1) * 2],
                            bfrag[nf >> 1][(nf & 1) * 2 + 1]);
        }
        __syncthreads();
    }

    // ---- epilogue ----
    const int g = lane >> 2, tg = lane & 3;
#pragma unroll
    for (int mi = 0; mi < 2; mi++) {
        const int r0 = wm + mi * 16 + g;
#pragma unroll
        for (int half = 0; half < 2; half++) {
            const int gr = mT * 128 + r0 + half * 8;
            if (gr >= NN) continue;
#pragma unroll
            for (int nf = 0; nf < 8; nf++) {
                const int c0 = wn + nf * 8 + tg * 2;
                float v0 = acc[mi][nf][half * 2];
                float v1 = acc[mi][nf][half * 2 + 1];
                if (!isV) {
                    const bool isQ = (nt < 2);
                    const int lc = (nt & 1) * 128 + c0;
                    const float* bptr = isQ ? bq : bk;
                    v0 += __ldg(bptr + lc);
                    v1 += __ldg(bptr + lc + 1);
                    __half* dst = isQ ? g_q : g_k;
                    __half2 p2 = __floats2half2_rn(v0, v1);
                    *(__half2*)(dst + (size_t)gr * 256 + lc) = p2;
                } else {
                    const int wc = (nt - 4) * 128 + c0;
                    v0 += __ldg(bv + wc);
                    v1 += __ldg(bv + wc + 1);
                    const int h = wc >> 5, d = wc & 31;
                    float* vp = out_v + (size_t)gr * 256 + d * 8 + h;
                    vp[0] = v0;
                    vp[8] = v1;
                }
            }
        }
    }
}

// ---------------------------------------------------------------------------
// Pass 1: 8 lanes per edge (one lane per head), 4 edges per warp.
// ---------------------------------------------------------------------------
__global__ void __launch_bounds__(256) edge_pass1(
    const int* __restrict__ edge,
    const float* __restrict__ ew,
    float* __restrict__ out_att)
{
    const int lane = threadIdx.x & 31;
    const int wid = threadIdx.x >> 5;
    const int e = blockIdx.x * 32 + wid * 4 + (lane >> 3);
    if (e >= EE) return;
    const int h = lane & 7;

    const int src = __ldg(edge + e);
    const int dst = __ldg(edge + EE + e);
    const float w = __ldg(ew + e);

    const uint4* qp = (const uint4*)(g_q + (size_t)src * 256 + h * 32);
    const uint4* kp = (const uint4*)(g_k + (size_t)dst * 256 + h * 32);

    uint4 q0 = qp[0], q1 = qp[1], q2 = qp[2], q3 = qp[3];
    uint4 k0 = kp[0], k1 = kp[1], k2 = kp[2], k3 = kp[3];

    float p = 0.f;
    const uint32_t qw[16] = {q0.x, q0.y, q0.z, q0.w, q1.x, q1.y, q1.z, q1.w,
                             q2.x, q2.y, q2.z, q2.w, q3.x, q3.y, q3.z, q3.w};
    const uint32_t kw[16] = {k0.x, k0.y, k0.z, k0.w, k1.x, k1.y, k1.z, k1.w,
                             k2.x, k2.y, k2.z, k2.w, k3.x, k3.y, k3.z, k3.w};
#pragma unroll
    for (int c = 0; c < 16; c++) {
        float2 qf = __half22float2(*reinterpret_cast<const __half2*>(&qw[c]));
        float2 kf = __half22float2(*reinterpret_cast<const __half2*>(&kw[c]));
        p = fmaf(qf.x, kf.x, p);
        p = fmaf(qf.y, kf.y, p);
    }

    const float ex = __expf(p * 0.17677669529663687f * w);   // 1/sqrt(32)
    out_att[(size_t)e * HH + h] = ex;
    atomicAdd(&g_sum[src * HH + h], ex);
}

// ---------------------------------------------------------------------------
// Pass 2: normalize.
// ---------------------------------------------------------------------------
__global__ void __launch_bounds__(256) edge_pass2(
    const int* __restrict__ edge,
    float* __restrict__ out_att)
{
    const int e = blockIdx.x * 256 + threadIdx.x;
    if (e >= EE) return;
    const int src = edge[e];

    const float4* sp = (const float4*)(g_sum + src * HH);
    float4 s0 = sp[0], s1 = sp[1];

    float4* ap = (float4*)(out_att + (size_t)e * HH);
    float4 a0 = ap[0], a1 = ap[1];

    a0.x = __fdividef(a0.x, s0.x + 1e-16f);
    a0.y = __fdividef(a0.y, s0.y + 1e-16f);
    a0.z = __fdividef(a0.z, s0.z + 1e-16f);
    a0.w = __fdividef(a0.w, s0.w + 1e-16f);
    a1.x = __fdividef(a1.x, s1.x + 1e-16f);
    a1.y = __fdividef(a1.y, s1.y + 1e-16f);
    a1.z = __fdividef(a1.z, s1.z + 1e-16f);
    a1.w = __fdividef(a1.w, s1.w + 1e-16f);

    ap[0] = a0; ap[1] = a1;
}

// ---------------------------------------------------------------------------
extern "C" void kernel_launch(void* const* d_in, const int* in_sizes, int n_in,
                              void* d_out, int out_size)
{
    const float* x    = (const float*)d_in[0];
    const int*   edge = (const int*)d_in[1];
    const float* ew   = (const float*)d_in[2];
    const float* Wq   = (const float*)d_in[3];
    const float* bq   = (const float*)d_in[4];
    const float* Wk   = (const float*)d_in[5];
    const float* bk   = (const float*)d_in[6];
    const float* Wv   = (const float*)d_in[7];
    const float* bv   = (const float*)d_in[8];

    float* out_att = (float*)d_out;
    float* out_v   = out_att + (size_t)EE * HH;

    convert_fp16<<<(XGROUPS + WGROUPS + ZGROUPS + 255) / 256, 256>>>(x, Wq, Wk, Wv);

    dim3 gGrid(6, (NN + 127) / 128);   // 6 x 391
    gemm_mma<<<gGrid, 256>>>(bq, bk, bv, out_v);

    edge_pass1<<<EE / 32, 256>>>(edge, ew, out_att);

    edge_pass2<<<(EE + 255) / 256, 256>>>(edge, out_att);
}

// round 7
// speedup vs baseline: 3.3498x; 1.2027x over previous
#include <cuda_runtime.h>
#include <cuda_fp16.h>
#include <cstdint>

#define NN 50000
#define EE 800000
#define KF 256
#define HH 8
#define WROWS 768   // [Wq;Wk;Wv]

// ---------------------------------------------------------------------------
// Scratch (static device globals; no allocation anywhere)
// ---------------------------------------------------------------------------
__device__ __align__(16) __half g_q[(size_t)NN * 256];
__device__ __align__(16) __half g_k[(size_t)NN * 256];
__device__ __align__(16) float g_sum[NN * HH];
__device__ __align__(16) __half g_xh[(size_t)NN * KF];
__device__ __align__(16) __half g_wh[(size_t)WROWS * KF];

// ---------------------------------------------------------------------------
__device__ __forceinline__ uint32_t smem_u32(const void* p) {
    uint32_t a;
    asm("{ .reg .u64 t; cvta.to.shared.u64 t, %1; cvt.u32.u64 %0, t; }" : "=r"(a) : "l"(p));
    return a;
}
__device__ __forceinline__ void ldsm_x4(uint32_t* r, uint32_t addr) {
    asm volatile("ldmatrix.sync.aligned.m8n8.x4.shared.b16 {%0,%1,%2,%3}, [%4];"
                 : "=r"(r[0]), "=r"(r[1]), "=r"(r[2]), "=r"(r[3]) : "r"(addr));
}
__device__ __forceinline__ void mma_f16(float* c, const uint32_t* a, uint32_t b0, uint32_t b1) {
    asm volatile(
        "mma.sync.aligned.m16n8k16.row.col.f32.f16.f16.f32 "
        "{%0,%1,%2,%3}, {%4,%5,%6,%7}, {%8,%9}, {%0,%1,%2,%3};"
        : "+f"(c[0]), "+f"(c[1]), "+f"(c[2]), "+f"(c[3])
        : "r"(a[0]), "r"(a[1]), "r"(a[2]), "r"(a[3]), "r"(b0), "r"(b1));
}
__device__ __forceinline__ void cp_async16(uint32_t smem_addr, const void* gptr, uint32_t src_bytes) {
    asm volatile("cp.async.cg.shared.global [%0], [%1], 16, %2;"
                 :: "r"(smem_addr), "l"(gptr), "r"(src_bytes) : "memory");
}
#define CP_COMMIT() asm volatile("cp.async.commit_group;" ::: "memory")
#define CP_WAIT(n)  asm volatile("cp.async.wait_group %0;" :: "n"(n) : "memory")

// ---------------------------------------------------------------------------
// Convert pre-pass: x -> g_xh (fp16); W concat -> g_wh (fp16); zero g_sum.
// ---------------------------------------------------------------------------
#define XGROUPS (NN * KF / 4)          // 3,200,000
#define WGROUPS (WROWS * KF / 4)       // 49,152
#define ZGROUPS (NN * HH / 4)          // 100,000
__global__ void __launch_bounds__(256) convert_fp16(
    const float* __restrict__ x,
    const float* __restrict__ Wq, const float* __restrict__ Wk, const float* __restrict__ Wv)
{
    int idx = blockIdx.x * 256 + threadIdx.x;
    if (idx >= XGROUPS + WGROUPS) {
        int z = idx - (XGROUPS + WGROUPS);
        if (z < ZGROUPS)
            *(float4*)(g_sum + (size_t)z * 4) = make_float4(0.f, 0.f, 0.f, 0.f);
        return;
    }

    const float* src;
    __half* dst;
    size_t off;
    if (idx < XGROUPS) {
        src = x; off = (size_t)idx * 4;
        dst = g_xh;
    } else {
        int widx = idx - XGROUPS;
        off = (size_t)widx * 4;
        size_t row = off / KF;
        const float* Wm = (row < 256) ? Wq : (row < 512) ? Wk : Wv;
        src = Wm - ((row < 256) ? 0 : (row < 512) ? 256 * KF : 512 * KF);
        dst = g_wh;
    }
    float4 v = *(const float4*)(src + off);
    __half2 p0 = __floats2half2_rn(v.x, v.y);
    __half2 p1 = __floats2half2_rn(v.z, v.w);
    uint2 u;
    u.x = *(uint32_t*)&p0; u.y = *(uint32_t*)&p1;
    *(uint2*)(dst + off) = u;
}

// ---------------------------------------------------------------------------
// Pipelined mma.sync QKV GEMM (fp16): C[N,768] = x @ W^T + b
// nt = ntBase + blockIdx.x : 0-1 -> g_q | 2-3 -> g_k | 4-5 -> out_v (staged)
// BM=128, BN=128, BK=32; 8 warps (32x64 warp tile); 2-stage cp.async pipeline.
// ---------------------------------------------------------------------------
#define SSTRIDE 10240u   // bytes per stage per tensor: 128*40*2

__global__ void __launch_bounds__(256) gemm_mma(
    int ntBase,
    const float* __restrict__ bq, const float* __restrict__ bk, const float* __restrict__ bv,
    float* __restrict__ out_v)
{
    __shared__ __align__(16) __half sA[2][128][40];
    __shared__ __align__(16) __half sB[2][128][40];

    const int t = threadIdx.x;
    const int wid = t >> 5;
    const int lane = t & 31;
    const int nt = ntBase + blockIdx.x;
    const int mT = blockIdx.y;      // 0..390
    const bool isV = (nt >= 4);

    const int wm = (wid >> 1) * 32;
    const int wn = (wid & 1) * 64;

    const uint32_t sAb = smem_u32(&sA[0][0][0]);
    const uint32_t sBb = smem_u32(&sB[0][0][0]);

    const int rA = (lane & 15);
    const int cA = (lane >> 4) << 3;
    const int rB = (lane & 7) + ((lane >> 4) << 3);
    const int cB = ((lane >> 3) & 1) << 3;

    uint32_t addrA[2], addrB[4];
#pragma unroll
    for (int mi = 0; mi < 2; mi++)
        addrA[mi] = sAb + (uint32_t)(wm + mi * 16 + rA) * 80u + (uint32_t)cA * 2u;
#pragma unroll
    for (int nf4 = 0; nf4 < 4; nf4++)
        addrB[nf4] = sBb + (uint32_t)(wn + nf4 * 16 + rB) * 80u + (uint32_t)cB * 2u;

    float acc[2][8][4];
#pragma unroll
    for (int mi = 0; mi < 2; mi++)
#pragma unroll
        for (int nf = 0; nf < 8; nf++)
#pragma unroll
            for (int i = 0; i < 4; i++) acc[mi][nf][i] = 0.f;

    const int lrow = t >> 1;
    const int lcg = (t & 1) * 16;
    const int growL = mT * 128 + lrow;
    const uint32_t aBytes = (growL < NN) ? 16u : 0u;
    const int brow = nt * 128 + lrow;

    const uint32_t dstA0 = sAb + (uint32_t)lrow * 80u + (uint32_t)lcg * 2u;
    const uint32_t dstB0 = sBb + (uint32_t)lrow * 80u + (uint32_t)lcg * 2u;

    auto issue = [&](int s) {
        const uint32_t st = (uint32_t)(s & 1) * SSTRIDE;
        const __half* ap = g_xh + (size_t)growL * KF + s * 32 + lcg;
        const __half* bp = g_wh + (size_t)brow * KF + s * 32 + lcg;
        cp_async16(dstA0 + st, ap, aBytes);
        cp_async16(dstA0 + st + 16, ap + 8, aBytes);
        cp_async16(dstB0 + st, bp, 16u);
        cp_async16(dstB0 + st + 16, bp + 8, 16u);
        CP_COMMIT();
    };

    issue(0);
#pragma unroll
    for (int s = 0; s < 8; s++) {
        if (s + 1 < 8) { issue(s + 1); CP_WAIT(1); }
        else           { CP_WAIT(0); }
        __syncthreads();

        const uint32_t st = (uint32_t)(s & 1) * SSTRIDE;
#pragma unroll
        for (int kk = 0; kk < 2; kk++) {
            uint32_t afrag[2][4];
            ldsm_x4(afrag[0], addrA[0] + st + kk * 32);
            ldsm_x4(afrag[1], addrA[1] + st + kk * 32);
            uint32_t bfrag[4][4];
#pragma unroll
            for (int nf4 = 0; nf4 < 4; nf4++)
                ldsm_x4(bfrag[nf4], addrB[nf4] + st + kk * 32);
#pragma unroll
            for (int mi = 0; mi < 2; mi++)
#pragma unroll
                for (int nf = 0; nf < 8; nf++)
                    mma_f16(acc[mi][nf], afrag[mi],
                            bfrag[nf >> 1][(nf & 1) * 2],
                            bfrag[nf >> 1][(nf & 1) * 2 + 1]);
        }
        __syncthreads();
    }

    const int g = lane >> 2, tg = lane & 3;

    if (!isV) {
        // ---- q/k epilogue: direct half2 stores (quad-contiguous 16B) ----
#pragma unroll
        for (int mi = 0; mi < 2; mi++) {
            const int r0 = wm + mi * 16 + g;
#pragma unroll
            for (int hh = 0; hh < 2; hh++) {
                const int gr = mT * 128 + r0 + hh * 8;
                if (gr >= NN) continue;
#pragma unroll
                for (int nf = 0; nf < 8; nf++) {
                    const int c0 = wn + nf * 8 + tg * 2;
                    const bool isQ = (nt < 2);
                    const int lc = (nt & 1) * 128 + c0;
                    const float* bptr = isQ ? bq : bk;
                    float v0 = acc[mi][nf][hh * 2]     + __ldg(bptr + lc);
                    float v1 = acc[mi][nf][hh * 2 + 1] + __ldg(bptr + lc + 1);
                    __half* dst = isQ ? g_q : g_k;
                    __half2 p2 = __floats2half2_rn(v0, v1);
                    *(__half2*)(dst + (size_t)gr * 256 + lc) = p2;
                }
            }
        }
    } else {
        // ---- v epilogue: stage 64-row halves in SMEM (compact 4d+h layout),
        //      then coalesced float4 stores to transposed out_v ----
        float* stg = (float*)&sA[0][0][0];    // reuse pipeline SMEM (>=33.8KB)
        const int wcBase = (nt - 4) * 128;
#pragma unroll
        for (int hf = 0; hf < 2; hf++) {
            __syncthreads();   // SMEM safe to reuse / previous readback done
            if ((wm >> 6) == hf) {
#pragma unroll
                for (int mi = 0; mi < 2; mi++) {
#pragma unroll
                    for (int hh = 0; hh < 2; hh++) {
                        const int lr = (wm & 63) + mi * 16 + g + hh * 8;
#pragma unroll
                        for (int nf = 0; nf < 8; nf++) {
                            const int c0 = wn + nf * 8 + tg * 2;
                            float v0 = acc[mi][nf][hh * 2]     + __ldg(bv + wcBase + c0);
                            float v1 = acc[mi][nf][hh * 2 + 1] + __ldg(bv + wcBase + c0 + 1);
                            // compact pos = 4*(c&31) + (c>>5)
                            stg[lr * 132 + 4 * (c0 & 31) + (c0 >> 5)] = v0;
                            stg[lr * 132 + 4 * ((c0 + 1) & 31) + ((c0 + 1) >> 5)] = v1;
                        }
                    }
                }
            }
            __syncthreads();
            // readback: 64 rows x 32 float4
#pragma unroll
            for (int it = 0; it < 8; it++) {
                const int idx = it * 256 + t;      // 0..2047
                const int r = idx >> 5, d = idx & 31;
                const int gr = mT * 128 + hf * 64 + r;
                if (gr < NN) {
                    float4 v4 = *(float4*)&stg[r * 132 + 4 * d];
                    *(float4*)(out_v + (size_t)gr * 256 + d * 8 + (nt - 4) * 4) = v4;
                }
            }
        }
    }
}

// ---------------------------------------------------------------------------
// Pass 1: 8 lanes per edge (one lane per head), 4 edges per warp.
// ---------------------------------------------------------------------------
__global__ void __launch_bounds__(256) edge_pass1(
    const int* __restrict__ edge,
    const float* __restrict__ ew,
    float* __restrict__ out_att)
{
    const int lane = threadIdx.x & 31;
    const int wid = threadIdx.x >> 5;
    const int e = blockIdx.x * 32 + wid * 4 + (lane >> 3);
    if (e >= EE) return;
    const int h = lane & 7;

    const int src = __ldg(edge + e);
    const int dst = __ldg(edge + EE + e);
    const float w = __ldg(ew + e);

    const uint4* qp = (const uint4*)(g_q + (size_t)src * 256 + h * 32);
    const uint4* kp = (const uint4*)(g_k + (size_t)dst * 256 + h * 32);

    uint4 q0 = qp[0], q1 = qp[1], q2 = qp[2], q3 = qp[3];
    uint4 k0 = kp[0], k1 = kp[1], k2 = kp[2], k3 = kp[3];

    float p = 0.f;
    const uint32_t qw[16] = {q0.x, q0.y, q0.z, q0.w, q1.x, q1.y, q1.z, q1.w,
                             q2.x, q2.y, q2.z, q2.w, q3.x, q3.y, q3.z, q3.w};
    const uint32_t kw[16] = {k0.x, k0.y, k0.z, k0.w, k1.x, k1.y, k1.z, k1.w,
                             k2.x, k2.y, k2.z, k2.w, k3.x, k3.y, k3.z, k3.w};
#pragma unroll
    for (int c = 0; c < 16; c++) {
        float2 qf = __half22float2(*reinterpret_cast<const __half2*>(&qw[c]));
        float2 kf = __half22float2(*reinterpret_cast<const __half2*>(&kw[c]));
        p = fmaf(qf.x, kf.x, p);
        p = fmaf(qf.y, kf.y, p);
    }

    const float ex = __expf(p * 0.17677669529663687f * w);   // 1/sqrt(32)
    out_att[(size_t)e * HH + h] = ex;
    atomicAdd(&g_sum[src * HH + h], ex);
}

// ---------------------------------------------------------------------------
// Pass 2: normalize.
// ---------------------------------------------------------------------------
__global__ void __launch_bounds__(256) edge_pass2(
    const int* __restrict__ edge,
    float* __restrict__ out_att)
{
    const int e = blockIdx.x * 256 + threadIdx.x;
    if (e >= EE) return;
    const int src = edge[e];

    const float4* sp = (const float4*)(g_sum + src * HH);
    float4 s0 = sp[0], s1 = sp[1];

    float4* ap = (float4*)(out_att + (size_t)e * HH);
    float4 a0 = ap[0], a1 = ap[1];

    a0.x = __fdividef(a0.x, s0.x + 1e-16f);
    a0.y = __fdividef(a0.y, s0.y + 1e-16f);
    a0.z = __fdividef(a0.z, s0.z + 1e-16f);
    a0.w = __fdividef(a0.w, s0.w + 1e-16f);
    a1.x = __fdividef(a1.x, s1.x + 1e-16f);
    a1.y = __fdividef(a1.y, s1.y + 1e-16f);
    a1.z = __fdividef(a1.z, s1.z + 1e-16f);
    a1.w = __fdividef(a1.w, s1.w + 1e-16f);

    ap[0] = a0; ap[1] = a1;
}

// ---------------------------------------------------------------------------
extern "C" void kernel_launch(void* const* d_in, const int* in_sizes, int n_in,
                              void* d_out, int out_size)
{
    const float* x    = (const float*)d_in[0];
    const int*   edge = (const int*)d_in[1];
    const float* ew   = (const float*)d_in[2];
    const float* Wq   = (const float*)d_in[3];
    const float* bq   = (const float*)d_in[4];
    const float* Wk   = (const float*)d_in[5];
    const float* bk   = (const float*)d_in[6];
    const float* Wv   = (const float*)d_in[7];
    const float* bv   = (const float*)d_in[8];

    float* out_att = (float*)d_out;
    float* out_v   = out_att + (size_t)EE * HH;

    // One-time stream/event setup (outside capture on the first/correctness call)
    static cudaStream_t s2 = nullptr;
    static cudaEvent_t evFork = nullptr, evJoin = nullptr;
    if (s2 == nullptr) {
        cudaStreamCreateWithFlags(&s2, cudaStreamNonBlocking);
        cudaEventCreateWithFlags(&evFork, cudaEventDisableTiming);
        cudaEventCreateWithFlags(&evJoin, cudaEventDisableTiming);
    }

    convert_fp16<<<(XGROUPS + WGROUPS + ZGROUPS + 255) / 256, 256>>>(x, Wq, Wk, Wv);

    // fork: v-GEMM runs concurrently with qk-GEMM + edge passes
    cudaEventRecord(evFork, 0);
    cudaStreamWaitEvent(s2, evFork, 0);

    dim3 gv(2, (NN + 127) / 128);
    gemm_mma<<<gv, 256, 0, s2>>>(4, bq, bk, bv, out_v);

    dim3 gqk(4, (NN + 127) / 128);
    gemm_mma<<<gqk, 256>>>(0, bq, bk, bv, out_v);

    edge_pass1<<<EE / 32, 256>>>(edge, ew, out_att);

    edge_pass2<<<(EE + 255) / 256, 256>>>(edge, out_att);

    // join
    cudaEventRecord(evJoin, s2);
    cudaStreamWaitEvent(0, evJoin, 0);
}

// round 8
// speedup vs baseline: 4.0267x; 1.2021x over previous
#include <cuda_runtime.h>
#include <cuda_fp16.h>
#include <cstdint>

#define NN 50000
#define EE 800000
#define KF 256
#define HH 8
#define WROWS 768   // [Wq;Wk;Wv]

// ---------------------------------------------------------------------------
// Scratch (static device globals; no allocation anywhere)
// ---------------------------------------------------------------------------
__device__ __align__(16) __half g_q[(size_t)NN * 256];
__device__ __align__(16) __half g_k[(size_t)NN * 256];
__device__ __align__(16) float g_sum[NN * HH];
__device__ __align__(16) __half g_xh[(size_t)NN * KF];
__device__ __align__(16) __half g_wh[(size_t)WROWS * KF];

// ---------------------------------------------------------------------------
__device__ __forceinline__ uint32_t smem_u32(const void* p) {
    uint32_t a;
    asm("{ .reg .u64 t; cvta.to.shared.u64 t, %1; cvt.u32.u64 %0, t; }" : "=r"(a) : "l"(p));
    return a;
}
__device__ __forceinline__ void ldsm_x4(uint32_t* r, uint32_t addr) {
    asm volatile("ldmatrix.sync.aligned.m8n8.x4.shared.b16 {%0,%1,%2,%3}, [%4];"
                 : "=r"(r[0]), "=r"(r[1]), "=r"(r[2]), "=r"(r[3]) : "r"(addr));
}
__device__ __forceinline__ void mma_f16(float* c, const uint32_t* a, uint32_t b0, uint32_t b1) {
    asm volatile(
        "mma.sync.aligned.m16n8k16.row.col.f32.f16.f16.f32 "
        "{%0,%1,%2,%3}, {%4,%5,%6,%7}, {%8,%9}, {%0,%1,%2,%3};"
        : "+f"(c[0]), "+f"(c[1]), "+f"(c[2]), "+f"(c[3])
        : "r"(a[0]), "r"(a[1]), "r"(a[2]), "r"(a[3]), "r"(b0), "r"(b1));
}
__device__ __forceinline__ void cp_async16(uint32_t smem_addr, const void* gptr, uint32_t src_bytes) {
    asm volatile("cp.async.cg.shared.global [%0], [%1], 16, %2;"
                 :: "r"(smem_addr), "l"(gptr), "r"(src_bytes) : "memory");
}
#define CP_COMMIT() asm volatile("cp.async.commit_group;" ::: "memory")
#define CP_WAIT(n)  asm volatile("cp.async.wait_group %0;" :: "n"(n) : "memory")

// ---------------------------------------------------------------------------
// Convert pre-pass: x -> g_xh (fp16); W concat -> g_wh (fp16); zero g_sum.
// ---------------------------------------------------------------------------
#define XGROUPS (NN * KF / 4)          // 3,200,000
#define WGROUPS (WROWS * KF / 4)       // 49,152
#define ZGROUPS (NN * HH / 4)          // 100,000
__global__ void __launch_bounds__(256) convert_fp16(
    const float* __restrict__ x,
    const float* __restrict__ Wq, const float* __restrict__ Wk, const float* __restrict__ Wv)
{
    int idx = blockIdx.x * 256 + threadIdx.x;
    if (idx >= XGROUPS + WGROUPS) {
        int z = idx - (XGROUPS + WGROUPS);
        if (z < ZGROUPS)
            *(float4*)(g_sum + (size_t)z * 4) = make_float4(0.f, 0.f, 0.f, 0.f);
        return;
    }

    const float* src;
    __half* dst;
    size_t off;
    if (idx < XGROUPS) {
        src = x; off = (size_t)idx * 4;
        dst = g_xh;
    } else {
        int widx = idx - XGROUPS;
        off = (size_t)widx * 4;
        size_t row = off / KF;
        const float* Wm = (row < 256) ? Wq : (row < 512) ? Wk : Wv;
        src = Wm - ((row < 256) ? 0 : (row < 512) ? 256 * KF : 512 * KF);
        dst = g_wh;
    }
    float4 v = *(const float4*)(src + off);
    __half2 p0 = __floats2half2_rn(v.x, v.y);
    __half2 p1 = __floats2half2_rn(v.z, v.w);
    uint2 u;
    u.x = *(uint32_t*)&p0; u.y = *(uint32_t*)&p1;
    *(uint2*)(dst + off) = u;
}

// ---------------------------------------------------------------------------
// Pipelined mma.sync QKV GEMM (fp16): C[N,768] = x @ W^T + b
// nt = ntBase + blockIdx.x : 0-1 -> g_q | 2-3 -> g_k | 4-5 -> out_v (staged)
// BM=128, BN=128, BK=32; 8 warps (32x64 warp tile); 2-stage cp.async pipeline.
// ---------------------------------------------------------------------------
#define SSTRIDE 10240u   // bytes per stage per tensor: 128*40*2

__global__ void __launch_bounds__(256) gemm_mma(
    int ntBase,
    const float* __restrict__ bq, const float* __restrict__ bk, const float* __restrict__ bv,
    float* __restrict__ out_v)
{
    __shared__ __align__(16) __half sA[2][128][40];
    __shared__ __align__(16) __half sB[2][128][40];

    const int t = threadIdx.x;
    const int wid = t >> 5;
    const int lane = t & 31;
    const int nt = ntBase + blockIdx.x;
    const int mT = blockIdx.y;      // 0..390
    const bool isV = (nt >= 4);

    const int wm = (wid >> 1) * 32;
    const int wn = (wid & 1) * 64;

    const uint32_t sAb = smem_u32(&sA[0][0][0]);
    const uint32_t sBb = smem_u32(&sB[0][0][0]);

    const int rA = (lane & 15);
    const int cA = (lane >> 4) << 3;
    const int rB = (lane & 7) + ((lane >> 4) << 3);
    const int cB = ((lane >> 3) & 1) << 3;

    uint32_t addrA[2], addrB[4];
#pragma unroll
    for (int mi = 0; mi < 2; mi++)
        addrA[mi] = sAb + (uint32_t)(wm + mi * 16 + rA) * 80u + (uint32_t)cA * 2u;
#pragma unroll
    for (int nf4 = 0; nf4 < 4; nf4++)
        addrB[nf4] = sBb + (uint32_t)(wn + nf4 * 16 + rB) * 80u + (uint32_t)cB * 2u;

    float acc[2][8][4];
#pragma unroll
    for (int mi = 0; mi < 2; mi++)
#pragma unroll
        for (int nf = 0; nf < 8; nf++)
#pragma unroll
            for (int i = 0; i < 4; i++) acc[mi][nf][i] = 0.f;

    const int lrow = t >> 1;
    const int lcg = (t & 1) * 16;
    const int growL = mT * 128 + lrow;
    const uint32_t aBytes = (growL < NN) ? 16u : 0u;
    const int brow = nt * 128 + lrow;

    const uint32_t dstA0 = sAb + (uint32_t)lrow * 80u + (uint32_t)lcg * 2u;
    const uint32_t dstB0 = sBb + (uint32_t)lrow * 80u + (uint32_t)lcg * 2u;

    auto issue = [&](int s) {
        const uint32_t st = (uint32_t)(s & 1) * SSTRIDE;
        const __half* ap = g_xh + (size_t)growL * KF + s * 32 + lcg;
        const __half* bp = g_wh + (size_t)brow * KF + s * 32 + lcg;
        cp_async16(dstA0 + st, ap, aBytes);
        cp_async16(dstA0 + st + 16, ap + 8, aBytes);
        cp_async16(dstB0 + st, bp, 16u);
        cp_async16(dstB0 + st + 16, bp + 8, 16u);
        CP_COMMIT();
    };

    issue(0);
#pragma unroll
    for (int s = 0; s < 8; s++) {
        if (s + 1 < 8) { issue(s + 1); CP_WAIT(1); }
        else           { CP_WAIT(0); }
        __syncthreads();

        const uint32_t st = (uint32_t)(s & 1) * SSTRIDE;
#pragma unroll
        for (int kk = 0; kk < 2; kk++) {
            uint32_t afrag[2][4];
            ldsm_x4(afrag[0], addrA[0] + st + kk * 32);
            ldsm_x4(afrag[1], addrA[1] + st + kk * 32);
            uint32_t bfrag[4][4];
#pragma unroll
            for (int nf4 = 0; nf4 < 4; nf4++)
                ldsm_x4(bfrag[nf4], addrB[nf4] + st + kk * 32);
#pragma unroll
            for (int mi = 0; mi < 2; mi++)
#pragma unroll
                for (int nf = 0; nf < 8; nf++)
                    mma_f16(acc[mi][nf], afrag[mi],
                            bfrag[nf >> 1][(nf & 1) * 2],
                            bfrag[nf >> 1][(nf & 1) * 2 + 1]);
        }
        __syncthreads();
    }

    const int g = lane >> 2, tg = lane & 3;

    if (!isV) {
        // ---- q/k epilogue: direct half2 stores ----
#pragma unroll
        for (int mi = 0; mi < 2; mi++) {
            const int r0 = wm + mi * 16 + g;
#pragma unroll
            for (int hh = 0; hh < 2; hh++) {
                const int gr = mT * 128 + r0 + hh * 8;
                if (gr >= NN) continue;
#pragma unroll
                for (int nf = 0; nf < 8; nf++) {
                    const int c0 = wn + nf * 8 + tg * 2;
                    const bool isQ = (nt < 2);
                    const int lc = (nt & 1) * 128 + c0;
                    const float* bptr = isQ ? bq : bk;
                    float v0 = acc[mi][nf][hh * 2]     + __ldg(bptr + lc);
                    float v1 = acc[mi][nf][hh * 2 + 1] + __ldg(bptr + lc + 1);
                    __half* dst = isQ ? g_q : g_k;
                    __half2 p2 = __floats2half2_rn(v0, v1);
                    *(__half2*)(dst + (size_t)gr * 256 + lc) = p2;
                }
            }
        }
    } else {
        // ---- v epilogue: stage 64-row halves in SMEM (compact 4d+h layout),
        //      then coalesced float4 stores to transposed out_v ----
        float* stg = (float*)&sA[0][0][0];    // reuse pipeline SMEM
        const int wcBase = (nt - 4) * 128;
#pragma unroll
        for (int hf = 0; hf < 2; hf++) {
            __syncthreads();
            if ((wm >> 6) == hf) {
#pragma unroll
                for (int mi = 0; mi < 2; mi++) {
#pragma unroll
                    for (int hh = 0; hh < 2; hh++) {
                        const int lr = (wm & 63) + mi * 16 + g + hh * 8;
#pragma unroll
                        for (int nf = 0; nf < 8; nf++) {
                            const int c0 = wn + nf * 8 + tg * 2;
                            float v0 = acc[mi][nf][hh * 2]     + __ldg(bv + wcBase + c0);
                            float v1 = acc[mi][nf][hh * 2 + 1] + __ldg(bv + wcBase + c0 + 1);
                            stg[lr * 132 + 4 * (c0 & 31) + (c0 >> 5)] = v0;
                            stg[lr * 132 + 4 * ((c0 + 1) & 31) + ((c0 + 1) >> 5)] = v1;
                        }
                    }
                }
            }
            __syncthreads();
#pragma unroll
            for (int it = 0; it < 8; it++) {
                const int idx = it * 256 + t;
                const int r = idx >> 5, d = idx & 31;
                const int gr = mT * 128 + hf * 64 + r;
                if (gr < NN) {
                    float4 v4 = *(float4*)&stg[r * 132 + 4 * d];
                    *(float4*)(out_v + (size_t)gr * 256 + d * 8 + (nt - 4) * 4) = v4;
                }
            }
        }
    }
}

// ---------------------------------------------------------------------------
// Pass 1: 4 edges/warp, 8 lanes/edge. Lane l loads contiguous 16B chunks
// (one 128B line per 8-lane group per instruction -> 4 wavefronts/warp/load).
// Chunk c = i*8+l belongs to head c>>2; shuffle-reduce in 4-lane groups,
// then redistribute so lane l owns head l (coalesced stores).
// ---------------------------------------------------------------------------
__global__ void __launch_bounds__(256) edge_pass1(
    const int* __restrict__ edge,
    const float* __restrict__ ew,
    float* __restrict__ out_att)
{
    const int lane = threadIdx.x & 31;
    const int wid = threadIdx.x >> 5;
    const int e = blockIdx.x * 32 + wid * 4 + (lane >> 3);
    const int l = lane & 7;

    const int src = __ldg(edge + e);
    const int dst = __ldg(edge + EE + e);
    const float w = __ldg(ew + e);

    const uint4* qb = (const uint4*)(g_q + (size_t)src * 256);
    const uint4* kb = (const uint4*)(g_k + (size_t)dst * 256);

    uint4 qv[4], kv[4];
#pragma unroll
    for (int i = 0; i < 4; i++) { qv[i] = qb[i * 8 + l]; kv[i] = kb[i * 8 + l]; }

    // pp[i] (after reduce) = logit of head 2i + (l>>2)
    float pp[4];
#pragma unroll
    for (int i = 0; i < 4; i++) {
        const uint32_t* qw = (const uint32_t*)&qv[i];
        const uint32_t* kw = (const uint32_t*)&kv[i];
        float p = 0.f;
#pragma unroll
        for (int c2 = 0; c2 < 4; c2++) {
            float2 qf = __half22float2(*(const __half2*)&qw[c2]);
            float2 kf = __half22float2(*(const __half2*)&kw[c2]);
            p = fmaf(qf.x, kf.x, p);
            p = fmaf(qf.y, kf.y, p);
        }
        p += __shfl_xor_sync(0xffffffffu, p, 1);
        p += __shfl_xor_sync(0xffffffffu, p, 2);
        pp[i] = p;
    }

    // redistribute: lane l wants head l = 2*(l>>1) + (l&1)
    const bool own = ((l & 1) == (l >> 2));
    float sel[4];
#pragma unroll
    for (int i = 0; i < 4; i++) {
        float pq = __shfl_xor_sync(0xffffffffu, pp[i], 4);
        sel[i] = own ? pp[i] : pq;
    }
    const int ii = l >> 1;
    float v = sel[0];
    if (ii == 1) v = sel[1];
    if (ii == 2) v = sel[2];
    if (ii == 3) v = sel[3];

    const float ex = __expf(v * 0.17677669529663687f * w);   // 1/sqrt(32)
    out_att[(size_t)e * HH + l] = ex;
    atomicAdd(&g_sum[src * HH + l], ex);
}

// ---------------------------------------------------------------------------
// Pass 2: normalize.
// ---------------------------------------------------------------------------
__global__ void __launch_bounds__(256) edge_pass2(
    const int* __restrict__ edge,
    float* __restrict__ out_att)
{
    const int e = blockIdx.x * 256 + threadIdx.x;
    if (e >= EE) return;
    const int src = edge[e];

    const float4* sp = (const float4*)(g_sum + src * HH);
    float4 s0 = sp[0], s1 = sp[1];

    float4* ap = (float4*)(out_att + (size_t)e * HH);
    float4 a0 = ap[0], a1 = ap[1];

    a0.x = __fdividef(a0.x, s0.x + 1e-16f);
    a0.y = __fdividef(a0.y, s0.y + 1e-16f);
    a0.z = __fdividef(a0.z, s0.z + 1e-16f);
    a0.w = __fdividef(a0.w, s0.w + 1e-16f);
    a1.x = __fdividef(a1.x, s1.x + 1e-16f);
    a1.y = __fdividef(a1.y, s1.y + 1e-16f);
    a1.z = __fdividef(a1.z, s1.z + 1e-16f);
    a1.w = __fdividef(a1.w, s1.w + 1e-16f);

    ap[0] = a0; ap[1] = a1;
}

// ---------------------------------------------------------------------------
extern "C" void kernel_launch(void* const* d_in, const int* in_sizes, int n_in,
                              void* d_out, int out_size)
{
    const float* x    = (const float*)d_in[0];
    const int*   edge = (const int*)d_in[1];
    const float* ew   = (const float*)d_in[2];
    const float* Wq   = (const float*)d_in[3];
    const float* bq   = (const float*)d_in[4];
    const float* Wk   = (const float*)d_in[5];
    const float* bk   = (const float*)d_in[6];
    const float* Wv   = (const float*)d_in[7];
    const float* bv   = (const float*)d_in[8];

    float* out_att = (float*)d_out;
    float* out_v   = out_att + (size_t)EE * HH;

    static cudaStream_t s2 = nullptr;
    static cudaEvent_t evFork = nullptr, evJoin = nullptr;
    if (s2 == nullptr) {
        cudaStreamCreateWithFlags(&s2, cudaStreamNonBlocking);
        cudaEventCreateWithFlags(&evFork, cudaEventDisableTiming);
        cudaEventCreateWithFlags(&evJoin, cudaEventDisableTiming);
    }

    convert_fp16<<<(XGROUPS + WGROUPS + ZGROUPS + 255) / 256, 256>>>(x, Wq, Wk, Wv);

    // fork: v-GEMM runs concurrently with qk-GEMM + edge passes
    cudaEventRecord(evFork, 0);
    cudaStreamWaitEvent(s2, evFork, 0);

    dim3 gv(2, (NN + 127) / 128);
    gemm_mma<<<gv, 256, 0, s2>>>(4, bq, bk, bv, out_v);

    dim3 gqk(4, (NN + 127) / 128);
    gemm_mma<<<gqk, 256>>>(0, bq, bk, bv, out_v);

    edge_pass1<<<EE / 32, 256>>>(edge, ew, out_att);

    edge_pass2<<<(EE + 255) / 256, 256>>>(edge, out_att);

    // join
    cudaEventRecord(evJoin, s2);
    cudaStreamWaitEvent(0, evJoin, 0);
}

// round 9
// speedup vs baseline: 4.4245x; 1.0988x over previous
#include <cuda_runtime.h>
#include <cuda_fp16.h>
#include <cstdint>

#define NN 50000
#define EE 800000
#define KF 256
#define HH 8
#define WROWS 768   // [Wq;Wk;Wv]

// ---------------------------------------------------------------------------
// Scratch (static device globals; no allocation anywhere)
// ---------------------------------------------------------------------------
__device__ __align__(16) __half g_q[(size_t)NN * 256];
__device__ __align__(16) __half g_k[(size_t)NN * 256];
__device__ __align__(16) float g_sum[NN * HH];
__device__ __align__(16) __half g_xh[(size_t)NN * KF];
__device__ __align__(16) __half g_wh[(size_t)WROWS * KF];

// ---------------------------------------------------------------------------
__device__ __forceinline__ uint32_t smem_u32(const void* p) {
    uint32_t a;
    asm("{ .reg .u64 t; cvta.to.shared.u64 t, %1; cvt.u32.u64 %0, t; }" : "=r"(a) : "l"(p));
    return a;
}
__device__ __forceinline__ void ldsm_x4(uint32_t* r, uint32_t addr) {
    asm volatile("ldmatrix.sync.aligned.m8n8.x4.shared.b16 {%0,%1,%2,%3}, [%4];"
                 : "=r"(r[0]), "=r"(r[1]), "=r"(r[2]), "=r"(r[3]) : "r"(addr));
}
__device__ __forceinline__ void mma_f16(float* c, const uint32_t* a, uint32_t b0, uint32_t b1) {
    asm volatile(
        "mma.sync.aligned.m16n8k16.row.col.f32.f16.f16.f32 "
        "{%0,%1,%2,%3}, {%4,%5,%6,%7}, {%8,%9}, {%0,%1,%2,%3};"
        : "+f"(c[0]), "+f"(c[1]), "+f"(c[2]), "+f"(c[3])
        : "r"(a[0]), "r"(a[1]), "r"(a[2]), "r"(a[3]), "r"(b0), "r"(b1));
}
__device__ __forceinline__ void cp_async16(uint32_t smem_addr, const void* gptr, uint32_t src_bytes) {
    asm volatile("cp.async.cg.shared.global [%0], [%1], 16, %2;"
                 :: "r"(smem_addr), "l"(gptr), "r"(src_bytes) : "memory");
}
#define CP_COMMIT() asm volatile("cp.async.commit_group;" ::: "memory")
#define CP_WAIT(n)  asm volatile("cp.async.wait_group %0;" :: "n"(n) : "memory")

// ---------------------------------------------------------------------------
// Convert pre-pass: x -> g_xh (fp16); W concat -> g_wh (fp16); zero g_sum.
// ---------------------------------------------------------------------------
#define XGROUPS (NN * KF / 4)          // 3,200,000
#define WGROUPS (WROWS * KF / 4)       // 49,152
#define ZGROUPS (NN * HH / 4)          // 100,000
__global__ void __launch_bounds__(256) convert_fp16(
    const float* __restrict__ x,
    const float* __restrict__ Wq, const float* __restrict__ Wk, const float* __restrict__ Wv)
{
    int idx = blockIdx.x * 256 + threadIdx.x;
    if (idx >= XGROUPS + WGROUPS) {
        int z = idx - (XGROUPS + WGROUPS);
        if (z < ZGROUPS)
            *(float4*)(g_sum + (size_t)z * 4) = make_float4(0.f, 0.f, 0.f, 0.f);
        return;
    }

    const float* src;
    __half* dst;
    size_t off;
    if (idx < XGROUPS) {
        src = x; off = (size_t)idx * 4;
        dst = g_xh;
    } else {
        int widx = idx - XGROUPS;
        off = (size_t)widx * 4;
        size_t row = off / KF;
        const float* Wm = (row < 256) ? Wq : (row < 512) ? Wk : Wv;
        src = Wm - ((row < 256) ? 0 : (row < 512) ? 256 * KF : 512 * KF);
        dst = g_wh;
    }
    float4 v = *(const float4*)(src + off);
    __half2 p0 = __floats2half2_rn(v.x, v.y);
    __half2 p1 = __floats2half2_rn(v.z, v.w);
    uint2 u;
    u.x = *(uint32_t*)&p0; u.y = *(uint32_t*)&p1;
    *(uint2*)(dst + off) = u;
}

// ---------------------------------------------------------------------------
// Pipelined mma.sync QKV GEMM (fp16): C[N,768] = x @ W^T + b
// nt = ntBase + blockIdx.x : 0-1 -> g_q | 2-3 -> g_k | 4-5 -> out_v (staged)
// BM=128, BN=128, BK=32; 8 warps; 4-stage cp.async circular pipeline,
// ONE __syncthreads per slice. Dynamic SMEM = 4 * 20480 = 81920 B.
// ---------------------------------------------------------------------------
#define NSTAGE 4
#define STAGE_BYTES 20480u   // A(128*40*2=10240) + B(10240)
#define B_OFF 10240u
#define SMEM_GEMM (NSTAGE * STAGE_BYTES)

extern __shared__ char dynsmem[];

__global__ void __launch_bounds__(256, 2) gemm_mma(
    int ntBase,
    const float* __restrict__ bq, const float* __restrict__ bk, const float* __restrict__ bv,
    float* __restrict__ out_v)
{
    const int t = threadIdx.x;
    const int wid = t >> 5;
    const int lane = t & 31;
    const int nt = ntBase + blockIdx.x;
    const int mT = blockIdx.y;      // 0..390
    const bool isV = (nt >= 4);

    const int wm = (wid >> 1) * 32;
    const int wn = (wid & 1) * 64;

    const uint32_t sb = smem_u32(dynsmem);

    const int rA = (lane & 15);
    const int cA = (lane >> 4) << 3;
    const int rB = (lane & 7) + ((lane >> 4) << 3);
    const int cB = ((lane >> 3) & 1) << 3;

    uint32_t addrA[2], addrB[4];
#pragma unroll
    for (int mi = 0; mi < 2; mi++)
        addrA[mi] = sb + (uint32_t)(wm + mi * 16 + rA) * 80u + (uint32_t)cA * 2u;
#pragma unroll
    for (int nf4 = 0; nf4 < 4; nf4++)
        addrB[nf4] = sb + B_OFF + (uint32_t)(wn + nf4 * 16 + rB) * 80u + (uint32_t)cB * 2u;

    float acc[2][8][4];
#pragma unroll
    for (int mi = 0; mi < 2; mi++)
#pragma unroll
        for (int nf = 0; nf < 8; nf++)
#pragma unroll
            for (int i = 0; i < 4; i++) acc[mi][nf][i] = 0.f;

    const int lrow = t >> 1;
    const int lcg = (t & 1) * 16;
    const int growL = mT * 128 + lrow;
    const uint32_t aBytes = (growL < NN) ? 16u : 0u;
    const int brow = nt * 128 + lrow;

    const uint32_t dstA0 = sb + (uint32_t)lrow * 80u + (uint32_t)lcg * 2u;
    const uint32_t dstB0 = sb + B_OFF + (uint32_t)lrow * 80u + (uint32_t)lcg * 2u;

    auto issue = [&](int s) {
        if (s < 8) {
            const uint32_t st = (uint32_t)(s & 3) * STAGE_BYTES;
            const __half* ap = g_xh + (size_t)growL * KF + s * 32 + lcg;
            const __half* bp = g_wh + (size_t)brow * KF + s * 32 + lcg;
            cp_async16(dstA0 + st, ap, aBytes);
            cp_async16(dstA0 + st + 16, ap + 8, aBytes);
            cp_async16(dstB0 + st, bp, 16u);
            cp_async16(dstB0 + st + 16, bp + 8, 16u);
        }
        CP_COMMIT();
    };

    issue(0); issue(1); issue(2);
#pragma unroll
    for (int s = 0; s < 8; s++) {
        CP_WAIT(2);
        __syncthreads();
        issue(s + 3);

        const uint32_t st = (uint32_t)(s & 3) * STAGE_BYTES;
#pragma unroll
        for (int kk = 0; kk < 2; kk++) {
            uint32_t afrag[2][4];
            ldsm_x4(afrag[0], addrA[0] + st + kk * 32);
            ldsm_x4(afrag[1], addrA[1] + st + kk * 32);
            uint32_t bfrag[4][4];
#pragma unroll
            for (int nf4 = 0; nf4 < 4; nf4++)
                ldsm_x4(bfrag[nf4], addrB[nf4] + st + kk * 32);
#pragma unroll
            for (int mi = 0; mi < 2; mi++)
#pragma unroll
                for (int nf = 0; nf < 8; nf++)
                    mma_f16(acc[mi][nf], afrag[mi],
                            bfrag[nf >> 1][(nf & 1) * 2],
                            bfrag[nf >> 1][(nf & 1) * 2 + 1]);
        }
    }

    const int g = lane >> 2, tg = lane & 3;

    if (!isV) {
        // ---- q/k epilogue: direct half2 stores ----
#pragma unroll
        for (int mi = 0; mi < 2; mi++) {
            const int r0 = wm + mi * 16 + g;
#pragma unroll
            for (int hh = 0; hh < 2; hh++) {
                const int gr = mT * 128 + r0 + hh * 8;
                if (gr >= NN) continue;
#pragma unroll
                for (int nf = 0; nf < 8; nf++) {
                    const int c0 = wn + nf * 8 + tg * 2;
                    const bool isQ = (nt < 2);
                    const int lc = (nt & 1) * 128 + c0;
                    const float* bptr = isQ ? bq : bk;
                    float v0 = acc[mi][nf][hh * 2]     + __ldg(bptr + lc);
                    float v1 = acc[mi][nf][hh * 2 + 1] + __ldg(bptr + lc + 1);
                    __half* dst = isQ ? g_q : g_k;
                    __half2 p2 = __floats2half2_rn(v0, v1);
                    *(__half2*)(dst + (size_t)gr * 256 + lc) = p2;
                }
            }
        }
    } else {
        // ---- v epilogue: stage 64-row halves in SMEM, coalesced float4 out ----
        float* stg = (float*)dynsmem;
        const int wcBase = (nt - 4) * 128;
#pragma unroll
        for (int hf = 0; hf < 2; hf++) {
            __syncthreads();
            if ((wm >> 6) == hf) {
#pragma unroll
                for (int mi = 0; mi < 2; mi++) {
#pragma unroll
                    for (int hh = 0; hh < 2; hh++) {
                        const int lr = (wm & 63) + mi * 16 + g + hh * 8;
#pragma unroll
                        for (int nf = 0; nf < 8; nf++) {
                            const int c0 = wn + nf * 8 + tg * 2;
                            float v0 = acc[mi][nf][hh * 2]     + __ldg(bv + wcBase + c0);
                            float v1 = acc[mi][nf][hh * 2 + 1] + __ldg(bv + wcBase + c0 + 1);
                            stg[lr * 132 + 4 * (c0 & 31) + (c0 >> 5)] = v0;
                            stg[lr * 132 + 4 * ((c0 + 1) & 31) + ((c0 + 1) >> 5)] = v1;
                        }
                    }
                }
            }
            __syncthreads();
#pragma unroll
            for (int it = 0; it < 8; it++) {
                const int idx = it * 256 + t;
                const int r = idx >> 5, d = idx & 31;
                const int gr = mT * 128 + hf * 64 + r;
                if (gr < NN) {
                    float4 v4 = *(float4*)&stg[r * 132 + 4 * d];
                    *(float4*)(out_v + (size_t)gr * 256 + d * 8 + (nt - 4) * 4) = v4;
                }
            }
        }
    }
}

// ---------------------------------------------------------------------------
// Pass 1: 4 edges/warp, 8 lanes/edge, contiguous 16B chunks per lane
// (minimal L1 wavefronts). Per-chunk dot in half2 (HFMA2), per-chunk fp32
// promote. 2 xor-shuffles reduce; lane l directly stores head 2*(l&3)+(l>>2).
// ---------------------------------------------------------------------------
__global__ void __launch_bounds__(256) edge_pass1(
    const int* __restrict__ edge,
    const float* __restrict__ ew,
    float* __restrict__ out_att)
{
    const int lane = threadIdx.x & 31;
    const int wid = threadIdx.x >> 5;
    const int e = blockIdx.x * 32 + wid * 4 + (lane >> 3);
    const int l = lane & 7;

    const int src = __ldg(edge + e);
    const int dst = __ldg(edge + EE + e);
    const float w = __ldg(ew + e);

    const uint4* qb = (const uint4*)(g_q + (size_t)src * 256);
    const uint4* kb = (const uint4*)(g_k + (size_t)dst * 256);

    uint4 qv[4], kv[4];
#pragma unroll
    for (int i = 0; i < 4; i++) { qv[i] = qb[i * 8 + l]; kv[i] = kb[i * 8 + l]; }

    // pp[i] (post-reduce) = logit of head 2i + (l>>2)
    float pp[4];
#pragma unroll
    for (int i = 0; i < 4; i++) {
        const __half2* qh = (const __half2*)&qv[i];
        const __half2* kh = (const __half2*)&kv[i];
        __half2 hacc = __hmul2(qh[0], kh[0]);
        hacc = __hfma2(qh[1], kh[1], hacc);
        hacc = __hfma2(qh[2], kh[2], hacc);
        hacc = __hfma2(qh[3], kh[3], hacc);
        float2 f2 = __half22float2(hacc);
        float p = f2.x + f2.y;
        p += __shfl_xor_sync(0xffffffffu, p, 1);
        p += __shfl_xor_sync(0xffffffffu, p, 2);
        pp[i] = p;
    }

    // lane l stores head h = 2*(l&3) + (l>>2), value pp[l&3]
    const int i3 = l & 3;
    float v = pp[0];
    if (i3 == 1) v = pp[1];
    if (i3 == 2) v = pp[2];
    if (i3 == 3) v = pp[3];
    const int h = 2 * i3 + (l >> 2);

    const float ex = __expf(v * 0.17677669529663687f * w);   // 1/sqrt(32)
    out_att[(size_t)e * HH + h] = ex;
    atomicAdd(&g_sum[src * HH + h], ex);
}

// ---------------------------------------------------------------------------
// Pass 2: normalize.
// ---------------------------------------------------------------------------
__global__ void __launch_bounds__(256) edge_pass2(
    const int* __restrict__ edge,
    float* __restrict__ out_att)
{
    const int e = blockIdx.x * 256 + threadIdx.x;
    if (e >= EE) return;
    const int src = edge[e];

    const float4* sp = (const float4*)(g_sum + src * HH);
    float4 s0 = sp[0], s1 = sp[1];

    float4* ap = (float4*)(out_att + (size_t)e * HH);
    float4 a0 = ap[0], a1 = ap[1];

    a0.x = __fdividef(a0.x, s0.x + 1e-16f);
    a0.y = __fdividef(a0.y, s0.y + 1e-16f);
    a0.z = __fdividef(a0.z, s0.z + 1e-16f);
    a0.w = __fdividef(a0.w, s0.w + 1e-16f);
    a1.x = __fdividef(a1.x, s1.x + 1e-16f);
    a1.y = __fdividef(a1.y, s1.y + 1e-16f);
    a1.z = __fdividef(a1.z, s1.z + 1e-16f);
    a1.w = __fdividef(a1.w, s1.w + 1e-16f);

    ap[0] = a0; ap[1] = a1;
}

// ---------------------------------------------------------------------------
extern "C" void kernel_launch(void* const* d_in, const int* in_sizes, int n_in,
                              void* d_out, int out_size)
{
    const float* x    = (const float*)d_in[0];
    const int*   edge = (const int*)d_in[1];
    const float* ew   = (const float*)d_in[2];
    const float* Wq   = (const float*)d_in[3];
    const float* bq   = (const float*)d_in[4];
    const float* Wk   = (const float*)d_in[5];
    const float* bk   = (const float*)d_in[6];
    const float* Wv   = (const float*)d_in[7];
    const float* bv   = (const float*)d_in[8];

    float* out_att = (float*)d_out;
    float* out_v   = out_att + (size_t)EE * HH;

    static cudaStream_t s2 = nullptr;
    static cudaEvent_t evFork = nullptr, evJoin = nullptr;
    if (s2 == nullptr) {
        cudaStreamCreateWithFlags(&s2, cudaStreamNonBlocking);
        cudaEventCreateWithFlags(&evFork, cudaEventDisableTiming);
        cudaEventCreateWithFlags(&evJoin, cudaEventDisableTiming);
        cudaFuncSetAttribute(gemm_mma, cudaFuncAttributeMaxDynamicSharedMemorySize, SMEM_GEMM);
    }

    convert_fp16<<<(XGROUPS + WGROUPS + ZGROUPS + 255) / 256, 256>>>(x, Wq, Wk, Wv);

    // fork: v-GEMM runs concurrently with qk-GEMM + edge passes
    cudaEventRecord(evFork, 0);
    cudaStreamWaitEvent(s2, evFork, 0);

    dim3 gv(2, (NN + 127) / 128);
    gemm_mma<<<gv, 256, SMEM_GEMM, s2>>>(4, bq, bk, bv, out_v);

    dim3 gqk(4, (NN + 127) / 128);
    gemm_mma<<<gqk, 256, SMEM_GEMM>>>(0, bq, bk, bv, out_v);

    edge_pass1<<<EE / 32, 256>>>(edge, ew, out_att);

    edge_pass2<<<(EE + 255) / 256, 256>>>(edge, out_att);

    // join
    cudaEventRecord(evJoin, s2);
    cudaStreamWaitEvent(0, evJoin, 0);
}